// round 1
// baseline (speedup 1.0000x reference)
#include <cuda_runtime.h>
#include <math.h>

// Problem constants
#define BATCH   64
#define NTOK    197
#define DIM     768
#define NHEAD   12
#define HDIM    64
#define MROWS   (BATCH * NTOK)     // 12608
#define KQKV    (3 * DIM)          // 2304

// Scratch (device globals — no allocation allowed)
__device__ float g_qkv[(size_t)MROWS * KQKV];   // [M, 2304] row-major
__device__ float g_attn[(size_t)MROWS * DIM];   // [M, 768]  row-major

// ---------------------------------------------------------------------------
// SGEMM (NT): C[m,n] = sum_k A[m,k] * B[n,k]   (both row-major, K contiguous)
// BM=BN=128, BK=16, 256 threads, 8x8 per thread.
// EPI==0: plain store. EPI==1: C += bias[n] + resid[m,n].
// N and K must be multiples of 128/16 (true here); M is predicated.
// ---------------------------------------------------------------------------
template <int EPI>
__global__ __launch_bounds__(256)
void sgemm_nt_kernel(const float* __restrict__ A,
                     const float* __restrict__ Bw,
                     float* __restrict__ C,
                     int M, int Nn, int K,
                     const float* __restrict__ bias,
                     const float* __restrict__ resid)
{
    constexpr int BM = 128, BN = 128, BK = 16;
    __shared__ float As[BK][BM];
    __shared__ float Bs[BK][BN];

    const int tid = threadIdx.x;
    const int tx = tid & 15;        // 0..15 -> col group
    const int ty = tid >> 4;        // 0..15 -> row group
    const int m0 = blockIdx.y * BM;
    const int n0 = blockIdx.x * BN;

    float acc[8][8];
#pragma unroll
    for (int i = 0; i < 8; i++)
#pragma unroll
        for (int j = 0; j < 8; j++) acc[i][j] = 0.f;

    for (int k0 = 0; k0 < K; k0 += BK) {
        // Load A tile (predicated on M), store transposed: As[k][m]
#pragma unroll
        for (int l = 0; l < 2; l++) {
            int f   = tid * 2 + l;          // 0..511 float4 id
            int row = f >> 2;               // 0..127
            int c4  = f & 3;                // 0..3
            float4 v = make_float4(0.f, 0.f, 0.f, 0.f);
            int gm = m0 + row;
            if (gm < M)
                v = *(const float4*)(A + (size_t)gm * K + k0 + c4 * 4);
            As[c4 * 4 + 0][row] = v.x;
            As[c4 * 4 + 1][row] = v.y;
            As[c4 * 4 + 2][row] = v.z;
            As[c4 * 4 + 3][row] = v.w;
        }
        // Load B tile (always in range)
#pragma unroll
        for (int l = 0; l < 2; l++) {
            int f   = tid * 2 + l;
            int row = f >> 2;
            int c4  = f & 3;
            float4 v = *(const float4*)(Bw + (size_t)(n0 + row) * K + k0 + c4 * 4);
            Bs[c4 * 4 + 0][row] = v.x;
            Bs[c4 * 4 + 1][row] = v.y;
            Bs[c4 * 4 + 2][row] = v.z;
            Bs[c4 * 4 + 3][row] = v.w;
        }
        __syncthreads();

#pragma unroll
        for (int kk = 0; kk < BK; kk++) {
            float a[8], b[8];
#pragma unroll
            for (int i = 0; i < 8; i++) a[i] = As[kk][ty * 8 + i];
#pragma unroll
            for (int j = 0; j < 8; j++) b[j] = Bs[kk][tx * 8 + j];
#pragma unroll
            for (int i = 0; i < 8; i++)
#pragma unroll
                for (int j = 0; j < 8; j++)
                    acc[i][j] += a[i] * b[j];
        }
        __syncthreads();
    }

    // Epilogue (vectorized float4 stores)
#pragma unroll
    for (int i = 0; i < 8; i++) {
        int gm = m0 + ty * 8 + i;
        if (gm >= M) continue;
        size_t rowbase = (size_t)gm * Nn + n0 + tx * 8;
#pragma unroll
        for (int jq = 0; jq < 2; jq++) {
            float4 v;
            v.x = acc[i][jq * 4 + 0];
            v.y = acc[i][jq * 4 + 1];
            v.z = acc[i][jq * 4 + 2];
            v.w = acc[i][jq * 4 + 3];
            if (EPI == 1) {
                int gn = n0 + tx * 8 + jq * 4;
                float4 bb = *(const float4*)(bias + gn);
                float4 rr = *(const float4*)(resid + rowbase + jq * 4);
                v.x += bb.x + rr.x;
                v.y += bb.y + rr.y;
                v.z += bb.z + rr.z;
                v.w += bb.w + rr.w;
            }
            *(float4*)(C + rowbase + jq * 4) = v;
        }
    }
}

// ---------------------------------------------------------------------------
// Fused attention: one block per (b, h). 256 threads = 8 warps.
// K kept transposed in smem (Kt[d][j], stride 224 -> conflict-free strided
// reads), V row-major [j][d]. Each warp handles one query at a time; each
// lane covers 7 strided keys. Diagonal self-mask -> -inf.
// Output written to g_attn in [B*N, H*HD] layout (ready for proj GEMM).
// ---------------------------------------------------------------------------
#define KT_STRIDE 224
#define ATTN_SMEM_FLOATS (HDIM * KT_STRIDE + NTOK * HDIM + 8 * HDIM + 8 * KT_STRIDE)

__global__ __launch_bounds__(256)
void attn_kernel(const float* __restrict__ qkv,
                 const float* __restrict__ scale,
                 float* __restrict__ attn_out)
{
    extern __shared__ float sm[];
    float* Kt  = sm;                              // [64][224]
    float* Vv  = Kt + HDIM * KT_STRIDE;           // [197][64]
    float* q_s = Vv + NTOK * HDIM;                // [8][64]
    float* p_s = q_s + 8 * HDIM;                  // [8][224]

    const int bh = blockIdx.x;
    const int b = bh / NHEAD, h = bh % NHEAD;
    const int tid = threadIdx.x;
    const int warp = tid >> 5, lane = tid & 31;

    // Load K (transposed) and V for this (b,h)
    for (int idx = tid; idx < NTOK * HDIM; idx += 256) {
        int j = idx >> 6;
        int d = idx & 63;
        size_t base = (size_t)(b * NTOK + j) * KQKV + h * HDIM + d;
        Kt[d * KT_STRIDE + j] = qkv[base + DIM];       // K at offset 768
        Vv[j * HDIM + d]      = qkv[base + 2 * DIM];   // V at offset 1536
    }
    __syncthreads();

    const float sc = scale[h];

    for (int i = warp; i < NTOK; i += 8) {
        // Load q (pre-scaled) into per-warp smem for broadcast
        size_t qrow = (size_t)(b * NTOK + i) * KQKV + h * HDIM;
        q_s[warp * HDIM + lane]      = qkv[qrow + lane] * sc;
        q_s[warp * HDIM + lane + 32] = qkv[qrow + lane + 32] * sc;
        __syncwarp();

        // Scores: lane covers keys j = lane + 32*jj, jj in 0..6
        float s[7];
#pragma unroll
        for (int jj = 0; jj < 7; jj++) s[jj] = 0.f;
#pragma unroll 8
        for (int d = 0; d < 64; d++) {
            float qd = q_s[warp * HDIM + d];
            const float* kr = &Kt[d * KT_STRIDE + lane];
#pragma unroll
            for (int jj = 0; jj < 7; jj++) s[jj] += qd * kr[jj * 32];
        }

        // Mask (assignment so any smem-pad garbage is overwritten) + max
        float mx = -INFINITY;
#pragma unroll
        for (int jj = 0; jj < 7; jj++) {
            int j = lane + jj * 32;
            if (j >= NTOK || j == i) s[jj] = -INFINITY;
            mx = fmaxf(mx, s[jj]);
        }
#pragma unroll
        for (int off = 16; off > 0; off >>= 1)
            mx = fmaxf(mx, __shfl_xor_sync(0xFFFFFFFFu, mx, off));

        float sum = 0.f;
#pragma unroll
        for (int jj = 0; jj < 7; jj++) {
            float p = __expf(s[jj] - mx);   // exp(-inf)=0 handles masks
            s[jj] = p;
            sum += p;
        }
#pragma unroll
        for (int off = 16; off > 0; off >>= 1)
            sum += __shfl_xor_sync(0xFFFFFFFFu, sum, off);

        // Share probabilities across the warp
#pragma unroll
        for (int jj = 0; jj < 7; jj++) {
            int j = lane + jj * 32;
            if (j < NTOK) p_s[warp * KT_STRIDE + j] = s[jj];
        }
        __syncwarp();

        // Weighted sum of V: lane owns dims (lane, lane+32)
        float o0 = 0.f, o1 = 0.f;
        for (int j = 0; j < NTOK; j++) {
            float pj = p_s[warp * KT_STRIDE + j];   // broadcast
            o0 += pj * Vv[j * HDIM + lane];
            o1 += pj * Vv[j * HDIM + lane + 32];
        }
        float inv = 1.f / sum;

        size_t orow = (size_t)(b * NTOK + i) * DIM + h * HDIM;
        attn_out[orow + lane]      = o0 * inv;
        attn_out[orow + lane + 32] = o1 * inv;
        __syncwarp();   // q_s/p_s reused next iteration
    }
}

// ---------------------------------------------------------------------------
// Launch
// ---------------------------------------------------------------------------
extern "C" void kernel_launch(void* const* d_in, const int* in_sizes, int n_in,
                              void* d_out, int out_size)
{
    const float* x      = (const float*)d_in[0];
    const float* scale  = (const float*)d_in[1];
    const float* w_qkv  = (const float*)d_in[2];
    const float* w_proj = (const float*)d_in[3];
    const float* b_proj = (const float*)d_in[4];
    float* out = (float*)d_out;

    float* qkv_ptr = nullptr;
    float* attn_ptr = nullptr;
    cudaGetSymbolAddress((void**)&qkv_ptr, g_qkv);
    cudaGetSymbolAddress((void**)&attn_ptr, g_attn);

    // 1) QKV projection: [12608,768] x [2304,768]^T -> [12608,2304]
    {
        dim3 grid(KQKV / 128, (MROWS + 127) / 128);
        sgemm_nt_kernel<0><<<grid, 256>>>(x, w_qkv, qkv_ptr,
                                          MROWS, KQKV, DIM, nullptr, nullptr);
    }

    // 2) Fused masked attention per (b,h)
    {
        size_t smem = (size_t)ATTN_SMEM_FLOATS * sizeof(float);
        cudaFuncSetAttribute(attn_kernel,
                             cudaFuncAttributeMaxDynamicSharedMemorySize,
                             (int)smem);
        attn_kernel<<<BATCH * NHEAD, 256, smem>>>(qkv_ptr, scale, attn_ptr);
    }

    // 3) Output projection + bias + residual: [12608,768] x [768,768]^T
    {
        dim3 grid(DIM / 128, (MROWS + 127) / 128);
        sgemm_nt_kernel<1><<<grid, 256>>>(attn_ptr, w_proj, out,
                                          MROWS, DIM, DIM, b_proj, x);
    }
}

// round 4
// speedup vs baseline: 1.6098x; 1.6098x over previous
#include <cuda_runtime.h>
#include <math.h>
#include <stdint.h>

// Problem constants
#define BATCH   64
#define NTOK    197
#define DIM     768
#define NHEAD   12
#define HDIM    64
#define MROWS   (BATCH * NTOK)     // 12608
#define KQKV    (3 * DIM)          // 2304

// Scratch (device globals — no allocation allowed)
__device__ float g_qkv[(size_t)MROWS * KQKV];   // [M, 2304] row-major
__device__ float g_attn[(size_t)MROWS * DIM];   // [M, 768]  row-major

// ---------------------------------------------------------------------------
// TF32 tensor-core GEMM (NT): C[m,n] = sum_k A[m,k] * B[n,k]
// A row-major [M,K], B row-major [N,K] (both K-contiguous -> mma row.col).
// BM=BN=128, BK=16, 256 threads (8 warps), warp tile 64x32.
// Double-buffered smem. EPI==1: C += bias[n] + resid[m,n].
// N, K multiples of 128/16; M predicated.
// ---------------------------------------------------------------------------
#define MMA_TF32(c, a0, a1, a2, a3, b0, b1)                                  \
    asm volatile(                                                            \
        "mma.sync.aligned.m16n8k8.row.col.f32.tf32.tf32.f32 "                \
        "{%0,%1,%2,%3},{%4,%5,%6,%7},{%8,%9},{%0,%1,%2,%3};"                 \
        : "+f"(c[0]), "+f"(c[1]), "+f"(c[2]), "+f"(c[3])                     \
        : "r"(a0), "r"(a1), "r"(a2), "r"(a3), "r"(b0), "r"(b1))

__device__ __forceinline__ uint32_t f2tf32(float x) {
    uint32_t u;
    asm("cvt.rna.tf32.f32 %0, %1;" : "=r"(u) : "f"(x));
    return u;
}

template <int EPI>
__global__ __launch_bounds__(256, 2)
void gemm_tf32_kernel(const float* __restrict__ A,
                      const float* __restrict__ Bw,
                      float* __restrict__ C,
                      int M, int Nn, int K,
                      const float* __restrict__ bias,
                      const float* __restrict__ resid)
{
    constexpr int BM = 128, BN = 128, BK = 16;
    constexpr int LDSW = BK + 4;   // 20 words -> conflict-free frag reads
    __shared__ uint32_t As[2][BM * LDSW];
    __shared__ uint32_t Bs[2][BN * LDSW];

    const int tid  = threadIdx.x;
    const int warp = tid >> 5, lane = tid & 31;
    const int wm = warp & 1;       // 0..1  (m offset wm*64)
    const int wn = warp >> 1;      // 0..3  (n offset wn*32)
    const int tq = lane >> 2;      // 0..7
    const int tr = lane & 3;       // 0..3
    const int m0 = blockIdx.y * BM;
    const int n0 = blockIdx.x * BN;

    // ldg mapping: each thread owns one row-half (8 consecutive k) of A and B
    const int lrow = tid >> 1;            // 0..127
    const int lcol = (tid & 1) * 8;       // 0 or 8

    float c[4][4][4];                     // c[mt][nt][4]
#pragma unroll
    for (int mt = 0; mt < 4; mt++)
#pragma unroll
        for (int nt = 0; nt < 4; nt++)
#pragma unroll
            for (int i = 0; i < 4; i++) c[mt][nt][i] = 0.f;

    const int nit = K / BK;
    float4 ra0, ra1, rb0, rb1;

    // ---- prologue: load tile 0 ----
    {
        const int gm = m0 + lrow;
        if (gm < M) {
            ra0 = *(const float4*)(A + (size_t)gm * K + lcol);
            ra1 = *(const float4*)(A + (size_t)gm * K + lcol + 4);
        } else {
            ra0 = ra1 = make_float4(0.f, 0.f, 0.f, 0.f);
        }
        rb0 = *(const float4*)(Bw + (size_t)(n0 + lrow) * K + lcol);
        rb1 = *(const float4*)(Bw + (size_t)(n0 + lrow) * K + lcol + 4);

        uint32_t* pa = &As[0][lrow * LDSW + lcol];
        pa[0] = f2tf32(ra0.x); pa[1] = f2tf32(ra0.y);
        pa[2] = f2tf32(ra0.z); pa[3] = f2tf32(ra0.w);
        pa[4] = f2tf32(ra1.x); pa[5] = f2tf32(ra1.y);
        pa[6] = f2tf32(ra1.z); pa[7] = f2tf32(ra1.w);
        uint32_t* pb = &Bs[0][lrow * LDSW + lcol];
        pb[0] = f2tf32(rb0.x); pb[1] = f2tf32(rb0.y);
        pb[2] = f2tf32(rb0.z); pb[3] = f2tf32(rb0.w);
        pb[4] = f2tf32(rb1.x); pb[5] = f2tf32(rb1.y);
        pb[6] = f2tf32(rb1.z); pb[7] = f2tf32(rb1.w);
    }
    __syncthreads();

    for (int it = 0; it < nit; it++) {
        const int cur = it & 1;
        // ---- prefetch next tile into registers ----
        if (it + 1 < nit) {
            const int k0 = (it + 1) * BK;
            const int gm = m0 + lrow;
            if (gm < M) {
                ra0 = *(const float4*)(A + (size_t)gm * K + k0 + lcol);
                ra1 = *(const float4*)(A + (size_t)gm * K + k0 + lcol + 4);
            } else {
                ra0 = ra1 = make_float4(0.f, 0.f, 0.f, 0.f);
            }
            rb0 = *(const float4*)(Bw + (size_t)(n0 + lrow) * K + k0 + lcol);
            rb1 = *(const float4*)(Bw + (size_t)(n0 + lrow) * K + k0 + lcol + 4);
        }

        // ---- compute on current buffer ----
#pragma unroll
        for (int ks = 0; ks < BK; ks += 8) {
            uint32_t af[4][4], bf[4][2];
#pragma unroll
            for (int mt = 0; mt < 4; mt++) {
                const int rb = wm * 64 + mt * 16;
                const uint32_t* base = &As[cur][0];
                af[mt][0] = base[(rb + tq) * LDSW + ks + tr];
                af[mt][1] = base[(rb + 8 + tq) * LDSW + ks + tr];
                af[mt][2] = base[(rb + tq) * LDSW + ks + 4 + tr];
                af[mt][3] = base[(rb + 8 + tq) * LDSW + ks + 4 + tr];
            }
#pragma unroll
            for (int nt = 0; nt < 4; nt++) {
                const int cb = wn * 32 + nt * 8 + tq;
                const uint32_t* base = &Bs[cur][0];
                bf[nt][0] = base[cb * LDSW + ks + tr];
                bf[nt][1] = base[cb * LDSW + ks + 4 + tr];
            }
#pragma unroll
            for (int mt = 0; mt < 4; mt++)
#pragma unroll
                for (int nt = 0; nt < 4; nt++)
                    MMA_TF32(c[mt][nt], af[mt][0], af[mt][1], af[mt][2], af[mt][3],
                             bf[nt][0], bf[nt][1]);
        }

        // ---- stage next tile into the other buffer ----
        if (it + 1 < nit) {
            const int nxt = (it + 1) & 1;
            uint32_t* pa = &As[nxt][lrow * LDSW + lcol];
            pa[0] = f2tf32(ra0.x); pa[1] = f2tf32(ra0.y);
            pa[2] = f2tf32(ra0.z); pa[3] = f2tf32(ra0.w);
            pa[4] = f2tf32(ra1.x); pa[5] = f2tf32(ra1.y);
            pa[6] = f2tf32(ra1.z); pa[7] = f2tf32(ra1.w);
            uint32_t* pb = &Bs[nxt][lrow * LDSW + lcol];
            pb[0] = f2tf32(rb0.x); pb[1] = f2tf32(rb0.y);
            pb[2] = f2tf32(rb0.z); pb[3] = f2tf32(rb0.w);
            pb[4] = f2tf32(rb1.x); pb[5] = f2tf32(rb1.y);
            pb[6] = f2tf32(rb1.z); pb[7] = f2tf32(rb1.w);
        }
        __syncthreads();
    }

    // ---- epilogue ----
#pragma unroll
    for (int mt = 0; mt < 4; mt++) {
        const int r0 = m0 + wm * 64 + mt * 16 + tq;
        const int r1 = r0 + 8;
#pragma unroll
        for (int nt = 0; nt < 4; nt++) {
            const int gn = n0 + wn * 32 + nt * 8 + 2 * tr;
            float2 bb = make_float2(0.f, 0.f);
            if (EPI == 1) bb = *(const float2*)(bias + gn);
            if (r0 < M) {
                float2 v = make_float2(c[mt][nt][0], c[mt][nt][1]);
                if (EPI == 1) {
                    float2 rr = *(const float2*)(resid + (size_t)r0 * Nn + gn);
                    v.x += bb.x + rr.x; v.y += bb.y + rr.y;
                }
                *(float2*)(C + (size_t)r0 * Nn + gn) = v;
            }
            if (r1 < M) {
                float2 v = make_float2(c[mt][nt][2], c[mt][nt][3]);
                if (EPI == 1) {
                    float2 rr = *(const float2*)(resid + (size_t)r1 * Nn + gn);
                    v.x += bb.x + rr.x; v.y += bb.y + rr.y;
                }
                *(float2*)(C + (size_t)r1 * Nn + gn) = v;
            }
        }
    }
}

// ---------------------------------------------------------------------------
// Fused attention: one block per (b, h). 256 threads = 8 warps.
// ---------------------------------------------------------------------------
#define KT_STRIDE 224
#define ATTN_SMEM_FLOATS (HDIM * KT_STRIDE + NTOK * HDIM + 8 * HDIM + 8 * KT_STRIDE)

__global__ __launch_bounds__(256)
void attn_kernel(const float* __restrict__ qkv,
                 const float* __restrict__ scale,
                 float* __restrict__ attn_out)
{
    extern __shared__ float sm[];
    float* Kt  = sm;                              // [64][224]
    float* Vv  = Kt + HDIM * KT_STRIDE;           // [197][64]
    float* q_s = Vv + NTOK * HDIM;                // [8][64]
    float* p_s = q_s + 8 * HDIM;                  // [8][224]

    const int bh = blockIdx.x;
    const int b = bh / NHEAD, h = bh % NHEAD;
    const int tid = threadIdx.x;
    const int warp = tid >> 5, lane = tid & 31;

    for (int idx = tid; idx < NTOK * HDIM; idx += 256) {
        int j = idx >> 6;
        int d = idx & 63;
        size_t base = (size_t)(b * NTOK + j) * KQKV + h * HDIM + d;
        Kt[d * KT_STRIDE + j] = qkv[base + DIM];
        Vv[j * HDIM + d]      = qkv[base + 2 * DIM];
    }
    __syncthreads();

    const float sc = scale[h];

    for (int i = warp; i < NTOK; i += 8) {
        size_t qrow = (size_t)(b * NTOK + i) * KQKV + h * HDIM;
        q_s[warp * HDIM + lane]      = qkv[qrow + lane] * sc;
        q_s[warp * HDIM + lane + 32] = qkv[qrow + lane + 32] * sc;
        __syncwarp();

        float s[7];
#pragma unroll
        for (int jj = 0; jj < 7; jj++) s[jj] = 0.f;
#pragma unroll 8
        for (int d = 0; d < 64; d++) {
            float qd = q_s[warp * HDIM + d];
            const float* kr = &Kt[d * KT_STRIDE + lane];
#pragma unroll
            for (int jj = 0; jj < 7; jj++) s[jj] += qd * kr[jj * 32];
        }

        float mx = -INFINITY;
#pragma unroll
        for (int jj = 0; jj < 7; jj++) {
            int j = lane + jj * 32;
            if (j >= NTOK || j == i) s[jj] = -INFINITY;
            mx = fmaxf(mx, s[jj]);
        }
#pragma unroll
        for (int off = 16; off > 0; off >>= 1)
            mx = fmaxf(mx, __shfl_xor_sync(0xFFFFFFFFu, mx, off));

        float sum = 0.f;
#pragma unroll
        for (int jj = 0; jj < 7; jj++) {
            float p = __expf(s[jj] - mx);
            s[jj] = p;
            sum += p;
        }
#pragma unroll
        for (int off = 16; off > 0; off >>= 1)
            sum += __shfl_xor_sync(0xFFFFFFFFu, sum, off);

#pragma unroll
        for (int jj = 0; jj < 7; jj++) {
            int j = lane + jj * 32;
            if (j < NTOK) p_s[warp * KT_STRIDE + j] = s[jj];
        }
        __syncwarp();

        float o0 = 0.f, o1 = 0.f;
        for (int j = 0; j < NTOK; j++) {
            float pj = p_s[warp * KT_STRIDE + j];
            o0 += pj * Vv[j * HDIM + lane];
            o1 += pj * Vv[j * HDIM + lane + 32];
        }
        float inv = 1.f / sum;

        size_t orow = (size_t)(b * NTOK + i) * DIM + h * HDIM;
        attn_out[orow + lane]      = o0 * inv;
        attn_out[orow + lane + 32] = o1 * inv;
        __syncwarp();
    }
}

// ---------------------------------------------------------------------------
// Launch
// ---------------------------------------------------------------------------
extern "C" void kernel_launch(void* const* d_in, const int* in_sizes, int n_in,
                              void* d_out, int out_size)
{
    const float* x      = (const float*)d_in[0];
    const float* scale  = (const float*)d_in[1];
    const float* w_qkv  = (const float*)d_in[2];
    const float* w_proj = (const float*)d_in[3];
    const float* b_proj = (const float*)d_in[4];
    float* out = (float*)d_out;

    float* qkv_ptr = nullptr;
    float* attn_ptr = nullptr;
    cudaGetSymbolAddress((void**)&qkv_ptr, g_qkv);
    cudaGetSymbolAddress((void**)&attn_ptr, g_attn);

    // 1) QKV projection: [12608,768] x [2304,768]^T -> [12608,2304]  (tf32 TC)
    {
        dim3 grid(KQKV / 128, (MROWS + 127) / 128);
        gemm_tf32_kernel<0><<<grid, 256>>>(x, w_qkv, qkv_ptr,
                                           MROWS, KQKV, DIM, nullptr, nullptr);
    }

    // 2) Fused masked attention per (b,h)
    {
        size_t smem = (size_t)ATTN_SMEM_FLOATS * sizeof(float);
        cudaFuncSetAttribute(attn_kernel,
                             cudaFuncAttributeMaxDynamicSharedMemorySize,
                             (int)smem);
        attn_kernel<<<BATCH * NHEAD, 256, smem>>>(qkv_ptr, scale, attn_ptr);
    }

    // 3) Output projection + bias + residual: [12608,768] x [768,768]^T (tf32 TC)
    {
        dim3 grid(DIM / 128, (MROWS + 127) / 128);
        gemm_tf32_kernel<1><<<grid, 256>>>(attn_ptr, w_proj, out,
                                           MROWS, DIM, DIM, b_proj, x);
    }
}

// round 7
// speedup vs baseline: 2.0736x; 1.2881x over previous
#include <cuda_runtime.h>
#include <math.h>
#include <stdint.h>

// Problem constants
#define BATCH   64
#define NTOK    197
#define DIM     768
#define NHEAD   12
#define HDIM    64
#define MROWS   (BATCH * NTOK)     // 12608
#define KQKV    (3 * DIM)          // 2304

// Scratch (device globals — no allocation allowed)
__device__ float g_qkv[(size_t)MROWS * KQKV];   // [M, 2304] row-major
__device__ float g_attn[(size_t)MROWS * DIM];   // [M, 768]  row-major

// ---------------------------------------------------------------------------
// Common tf32 mma helpers
// ---------------------------------------------------------------------------
#define MMA_TF32(c, a0, a1, a2, a3, b0, b1)                                  \
    asm volatile(                                                            \
        "mma.sync.aligned.m16n8k8.row.col.f32.tf32.tf32.f32 "                \
        "{%0,%1,%2,%3},{%4,%5,%6,%7},{%8,%9},{%0,%1,%2,%3};"                 \
        : "+f"(c[0]), "+f"(c[1]), "+f"(c[2]), "+f"(c[3])                     \
        : "r"(a0), "r"(a1), "r"(a2), "r"(a3), "r"(b0), "r"(b1))

__device__ __forceinline__ uint32_t f2tf32(float x) {
    uint32_t u;
    asm("cvt.rna.tf32.f32 %0, %1;" : "=r"(u) : "f"(x));
    return u;
}

// ---------------------------------------------------------------------------
// TF32 tensor-core GEMM (NT): C[m,n] = sum_k A[m,k] * B[n,k]   (unchanged R4)
// ---------------------------------------------------------------------------
template <int EPI>
__global__ __launch_bounds__(256, 2)
void gemm_tf32_kernel(const float* __restrict__ A,
                      const float* __restrict__ Bw,
                      float* __restrict__ C,
                      int M, int Nn, int K,
                      const float* __restrict__ bias,
                      const float* __restrict__ resid)
{
    constexpr int BM = 128, BN = 128, BK = 16;
    constexpr int LDSW = BK + 4;
    __shared__ uint32_t As[2][BM * LDSW];
    __shared__ uint32_t Bs[2][BN * LDSW];

    const int tid  = threadIdx.x;
    const int warp = tid >> 5, lane = tid & 31;
    const int wm = warp & 1;
    const int wn = warp >> 1;
    const int tq = lane >> 2;
    const int tr = lane & 3;
    const int m0 = blockIdx.y * BM;
    const int n0 = blockIdx.x * BN;

    const int lrow = tid >> 1;
    const int lcol = (tid & 1) * 8;

    float c[4][4][4];
#pragma unroll
    for (int mt = 0; mt < 4; mt++)
#pragma unroll
        for (int nt = 0; nt < 4; nt++)
#pragma unroll
            for (int i = 0; i < 4; i++) c[mt][nt][i] = 0.f;

    const int nit = K / BK;
    float4 ra0, ra1, rb0, rb1;

    {
        const int gm = m0 + lrow;
        if (gm < M) {
            ra0 = *(const float4*)(A + (size_t)gm * K + lcol);
            ra1 = *(const float4*)(A + (size_t)gm * K + lcol + 4);
        } else {
            ra0 = ra1 = make_float4(0.f, 0.f, 0.f, 0.f);
        }
        rb0 = *(const float4*)(Bw + (size_t)(n0 + lrow) * K + lcol);
        rb1 = *(const float4*)(Bw + (size_t)(n0 + lrow) * K + lcol + 4);

        uint32_t* pa = &As[0][lrow * LDSW + lcol];
        pa[0] = f2tf32(ra0.x); pa[1] = f2tf32(ra0.y);
        pa[2] = f2tf32(ra0.z); pa[3] = f2tf32(ra0.w);
        pa[4] = f2tf32(ra1.x); pa[5] = f2tf32(ra1.y);
        pa[6] = f2tf32(ra1.z); pa[7] = f2tf32(ra1.w);
        uint32_t* pb = &Bs[0][lrow * LDSW + lcol];
        pb[0] = f2tf32(rb0.x); pb[1] = f2tf32(rb0.y);
        pb[2] = f2tf32(rb0.z); pb[3] = f2tf32(rb0.w);
        pb[4] = f2tf32(rb1.x); pb[5] = f2tf32(rb1.y);
        pb[6] = f2tf32(rb1.z); pb[7] = f2tf32(rb1.w);
    }
    __syncthreads();

    for (int it = 0; it < nit; it++) {
        const int cur = it & 1;
        if (it + 1 < nit) {
            const int k0 = (it + 1) * BK;
            const int gm = m0 + lrow;
            if (gm < M) {
                ra0 = *(const float4*)(A + (size_t)gm * K + k0 + lcol);
                ra1 = *(const float4*)(A + (size_t)gm * K + k0 + lcol + 4);
            } else {
                ra0 = ra1 = make_float4(0.f, 0.f, 0.f, 0.f);
            }
            rb0 = *(const float4*)(Bw + (size_t)(n0 + lrow) * K + k0 + lcol);
            rb1 = *(const float4*)(Bw + (size_t)(n0 + lrow) * K + k0 + lcol + 4);
        }

#pragma unroll
        for (int ks = 0; ks < BK; ks += 8) {
            uint32_t af[4][4], bf[4][2];
#pragma unroll
            for (int mt = 0; mt < 4; mt++) {
                const int rb = wm * 64 + mt * 16;
                const uint32_t* base = &As[cur][0];
                af[mt][0] = base[(rb + tq) * LDSW + ks + tr];
                af[mt][1] = base[(rb + 8 + tq) * LDSW + ks + tr];
                af[mt][2] = base[(rb + tq) * LDSW + ks + 4 + tr];
                af[mt][3] = base[(rb + 8 + tq) * LDSW + ks + 4 + tr];
            }
#pragma unroll
            for (int nt = 0; nt < 4; nt++) {
                const int cb = wn * 32 + nt * 8 + tq;
                const uint32_t* base = &Bs[cur][0];
                bf[nt][0] = base[cb * LDSW + ks + tr];
                bf[nt][1] = base[cb * LDSW + ks + 4 + tr];
            }
#pragma unroll
            for (int mt = 0; mt < 4; mt++)
#pragma unroll
                for (int nt = 0; nt < 4; nt++)
                    MMA_TF32(c[mt][nt], af[mt][0], af[mt][1], af[mt][2], af[mt][3],
                             bf[nt][0], bf[nt][1]);
        }

        if (it + 1 < nit) {
            const int nxt = (it + 1) & 1;
            uint32_t* pa = &As[nxt][lrow * LDSW + lcol];
            pa[0] = f2tf32(ra0.x); pa[1] = f2tf32(ra0.y);
            pa[2] = f2tf32(ra0.z); pa[3] = f2tf32(ra0.w);
            pa[4] = f2tf32(ra1.x); pa[5] = f2tf32(ra1.y);
            pa[6] = f2tf32(ra1.z); pa[7] = f2tf32(ra1.w);
            uint32_t* pb = &Bs[nxt][lrow * LDSW + lcol];
            pb[0] = f2tf32(rb0.x); pb[1] = f2tf32(rb0.y);
            pb[2] = f2tf32(rb0.z); pb[3] = f2tf32(rb0.w);
            pb[4] = f2tf32(rb1.x); pb[5] = f2tf32(rb1.y);
            pb[6] = f2tf32(rb1.z); pb[7] = f2tf32(rb1.w);
        }
        __syncthreads();
    }

#pragma unroll
    for (int mt = 0; mt < 4; mt++) {
        const int r0 = m0 + wm * 64 + mt * 16 + tq;
        const int r1 = r0 + 8;
#pragma unroll
        for (int nt = 0; nt < 4; nt++) {
            const int gn = n0 + wn * 32 + nt * 8 + 2 * tr;
            float2 bb = make_float2(0.f, 0.f);
            if (EPI == 1) bb = *(const float2*)(bias + gn);
            if (r0 < M) {
                float2 v = make_float2(c[mt][nt][0], c[mt][nt][1]);
                if (EPI == 1) {
                    float2 rr = *(const float2*)(resid + (size_t)r0 * Nn + gn);
                    v.x += bb.x + rr.x; v.y += bb.y + rr.y;
                }
                *(float2*)(C + (size_t)r0 * Nn + gn) = v;
            }
            if (r1 < M) {
                float2 v = make_float2(c[mt][nt][2], c[mt][nt][3]);
                if (EPI == 1) {
                    float2 rr = *(const float2*)(resid + (size_t)r1 * Nn + gn);
                    v.x += bb.x + rr.x; v.y += bb.y + rr.y;
                }
                *(float2*)(C + (size_t)r1 * Nn + gn) = v;
            }
        }
    }
}

// ---------------------------------------------------------------------------
// Tensor-core attention. Block = (b, h, qtile of 64 queries). 256 thr, 8 warps.
// S = Q·K^T (mma, scale folded into Q), register softmax with diag mask,
// P (tf32) overlays the dead K tile in smem, O = P·V^T (mma), store to g_attn.
// Keys padded to 224 (masked); queries padded to 64 (stores guarded).
// ---------------------------------------------------------------------------
#define QT    64
#define NKPAD 224
#define QK_LD 68    // stride for Qs/Ks: (4*tq+tr)%32 unique -> conflict-free
#define PV_LD 228   // stride for P/VT: same property

// smem word offsets
#define QS_OFF   0                               // 64*68   = 4352
#define KS_OFF   (QS_OFF + QT * QK_LD)           // 224*68  = 15232
#define VT_OFF   (KS_OFF + NKPAD * QK_LD)        // 64*228  = 14592
#define PMAX_OFF (VT_OFF + HDIM * PV_LD)         // 2*64
#define PSUM_OFF (PMAX_OFF + 2 * QT)             // 2*64
#define ATTN2_SMEM_WORDS (PSUM_OFF + 2 * QT)     // 34432 words = 137728 B

__global__ __launch_bounds__(256, 1)
void attn_mma_kernel(const float* __restrict__ qkv,
                     const float* __restrict__ scale,
                     float* __restrict__ attn_out)
{
    extern __shared__ uint32_t smw[];
    uint32_t* Qs = smw + QS_OFF;
    uint32_t* Ks = smw + KS_OFF;
    uint32_t* VT = smw + VT_OFF;
    float* Pp    = (float*)(smw + KS_OFF);       // overlay (written after Ks dead)
    float* pmax  = (float*)(smw + PMAX_OFF);
    float* psum  = (float*)(smw + PSUM_OFF);

    const int bh = blockIdx.x;
    const int b = bh / NHEAD, h = bh % NHEAD;
    const int q0 = blockIdx.y * QT;
    const int tid = threadIdx.x;
    const int warp = tid >> 5, lane = tid & 31;
    const int tq = lane >> 2, tr = lane & 3;
    const float sc = scale[h];

    // ---- load Q (scaled), K, V^T into smem as tf32 ----
    for (int idx = tid; idx < QT * 16; idx += 256) {          // Q: 64 rows x 16 f4
        int r = idx >> 4, c4 = (idx & 15) * 4;
        int q = q0 + r;
        if (q < NTOK) {
            float4 v = *(const float4*)(qkv + (size_t)(b * NTOK + q) * KQKV + h * HDIM + c4);
            uint32_t* p = &Qs[r * QK_LD + c4];
            p[0] = f2tf32(v.x * sc); p[1] = f2tf32(v.y * sc);
            p[2] = f2tf32(v.z * sc); p[3] = f2tf32(v.w * sc);
        }
    }
    for (int idx = tid; idx < NTOK * 16; idx += 256) {        // K: 197 rows x 16 f4
        int j = idx >> 4, c4 = (idx & 15) * 4;
        float4 v = *(const float4*)(qkv + (size_t)(b * NTOK + j) * KQKV + DIM + h * HDIM + c4);
        uint32_t* p = &Ks[j * QK_LD + c4];
        p[0] = f2tf32(v.x); p[1] = f2tf32(v.y);
        p[2] = f2tf32(v.z); p[3] = f2tf32(v.w);
    }
    // zero VT padding columns (keys 196..227) so 0*garbage can't NaN
    for (int idx = tid; idx < HDIM * 32; idx += 256) {
        int d = idx >> 5, j = 196 + (idx & 31);
        VT[d * PV_LD + j] = 0;
    }
    __syncthreads();   // ensure pad-zeroing precedes transposed fill (disjoint anyway; cheap)
    for (int idx = tid; idx < NTOK * 16; idx += 256) {        // V -> VT transpose
        int j = idx >> 4, c4 = (idx & 15) * 4;
        float4 v = *(const float4*)(qkv + (size_t)(b * NTOK + j) * KQKV + 2 * DIM + h * HDIM + c4);
        VT[(c4 + 0) * PV_LD + j] = f2tf32(v.x);
        VT[(c4 + 1) * PV_LD + j] = f2tf32(v.y);
        VT[(c4 + 2) * PV_LD + j] = f2tf32(v.z);
        VT[(c4 + 3) * PV_LD + j] = f2tf32(v.w);
    }
    __syncthreads();

    // ---- S = Q K^T : warp = (mfrag mf, key-half ng). 14 n-frags per warp ----
    const int mf = warp & 3;          // 16-query frag
    const int ng = warp >> 2;         // 0/1 -> keys [ng*112, ng*112+112)
    float c[14][4];
#pragma unroll
    for (int nf = 0; nf < 14; nf++)
#pragma unroll
        for (int i = 0; i < 4; i++) c[nf][i] = 0.f;

#pragma unroll
    for (int ks = 0; ks < 8; ks++) {
        const int kb = ks * 8;
        uint32_t a0 = Qs[(mf * 16 + tq) * QK_LD + kb + tr];
        uint32_t a1 = Qs[(mf * 16 + 8 + tq) * QK_LD + kb + tr];
        uint32_t a2 = Qs[(mf * 16 + tq) * QK_LD + kb + 4 + tr];
        uint32_t a3 = Qs[(mf * 16 + 8 + tq) * QK_LD + kb + 4 + tr];
#pragma unroll
        for (int nf = 0; nf < 14; nf++) {
            const int kn = ng * 112 + nf * 8 + tq;
            uint32_t b0 = Ks[kn * QK_LD + kb + tr];
            uint32_t b1 = Ks[kn * QK_LD + kb + 4 + tr];
            MMA_TF32(c[nf], a0, a1, a2, a3, b0, b1);
        }
    }

    // ---- mask + row max (this warp's 112-key half) ----
    const int i0 = q0 + mf * 16 + tq;
    const int i1 = i0 + 8;
    float mx0 = -INFINITY, mx1 = -INFINITY;
#pragma unroll
    for (int nf = 0; nf < 14; nf++) {
        const int j0 = ng * 112 + nf * 8 + 2 * tr;
        const int j1 = j0 + 1;
        c[nf][0] = (j0 >= NTOK || j0 == i0) ? -INFINITY : c[nf][0];
        c[nf][1] = (j1 >= NTOK || j1 == i0) ? -INFINITY : c[nf][1];
        c[nf][2] = (j0 >= NTOK || j0 == i1) ? -INFINITY : c[nf][2];
        c[nf][3] = (j1 >= NTOK || j1 == i1) ? -INFINITY : c[nf][3];
        mx0 = fmaxf(mx0, fmaxf(c[nf][0], c[nf][1]));
        mx1 = fmaxf(mx1, fmaxf(c[nf][2], c[nf][3]));
    }
    mx0 = fmaxf(mx0, __shfl_xor_sync(0xFFFFFFFFu, mx0, 1));
    mx0 = fmaxf(mx0, __shfl_xor_sync(0xFFFFFFFFu, mx0, 2));
    mx1 = fmaxf(mx1, __shfl_xor_sync(0xFFFFFFFFu, mx1, 1));
    mx1 = fmaxf(mx1, __shfl_xor_sync(0xFFFFFFFFu, mx1, 2));
    if (tr == 0) {
        pmax[ng * QT + mf * 16 + tq]     = mx0;
        pmax[ng * QT + mf * 16 + tq + 8] = mx1;
    }
    __syncthreads();
    const float M0 = fmaxf(pmax[mf * 16 + tq],     pmax[QT + mf * 16 + tq]);
    const float M1 = fmaxf(pmax[mf * 16 + tq + 8], pmax[QT + mf * 16 + tq + 8]);

    // ---- exp + row sum ----
    float s0 = 0.f, s1 = 0.f;
#pragma unroll
    for (int nf = 0; nf < 14; nf++) {
        c[nf][0] = __expf(c[nf][0] - M0);
        c[nf][1] = __expf(c[nf][1] - M0);
        c[nf][2] = __expf(c[nf][2] - M1);
        c[nf][3] = __expf(c[nf][3] - M1);
        s0 += c[nf][0] + c[nf][1];
        s1 += c[nf][2] + c[nf][3];
    }
    s0 += __shfl_xor_sync(0xFFFFFFFFu, s0, 1);
    s0 += __shfl_xor_sync(0xFFFFFFFFu, s0, 2);
    s1 += __shfl_xor_sync(0xFFFFFFFFu, s1, 1);
    s1 += __shfl_xor_sync(0xFFFFFFFFu, s1, 2);
    if (tr == 0) {
        psum[ng * QT + mf * 16 + tq]     = s0;
        psum[ng * QT + mf * 16 + tq + 8] = s1;
    }
    __syncthreads();   // also: last read of Ks was the S-mma; Pp overlay now safe
    const float inv0 = 1.f / (psum[mf * 16 + tq]     + psum[QT + mf * 16 + tq]);
    const float inv1 = 1.f / (psum[mf * 16 + tq + 8] + psum[QT + mf * 16 + tq + 8]);

    // ---- write P (tf32, normalized) into overlay ----
    uint32_t* Pu = (uint32_t*)Pp;
#pragma unroll
    for (int nf = 0; nf < 14; nf++) {
        const int col = ng * 112 + nf * 8 + 2 * tr;
        uint2 w0, w1;
        w0.x = f2tf32(c[nf][0] * inv0); w0.y = f2tf32(c[nf][1] * inv0);
        w1.x = f2tf32(c[nf][2] * inv1); w1.y = f2tf32(c[nf][3] * inv1);
        *(uint2*)&Pu[(mf * 16 + tq) * PV_LD + col]     = w0;
        *(uint2*)&Pu[(mf * 16 + 8 + tq) * PV_LD + col] = w1;
    }
    __syncthreads();

    // ---- O = P V^T : warp = (mfrag mf, dim-half ng -> 4 n-frags of 8 dims) ----
    float o[4][4];
#pragma unroll
    for (int nf = 0; nf < 4; nf++)
#pragma unroll
        for (int i = 0; i < 4; i++) o[nf][i] = 0.f;

#pragma unroll
    for (int kc = 0; kc < 28; kc++) {
        const int kb = kc * 8;
        uint32_t a0 = Pu[(mf * 16 + tq) * PV_LD + kb + tr];
        uint32_t a1 = Pu[(mf * 16 + 8 + tq) * PV_LD + kb + tr];
        uint32_t a2 = Pu[(mf * 16 + tq) * PV_LD + kb + 4 + tr];
        uint32_t a3 = Pu[(mf * 16 + 8 + tq) * PV_LD + kb + 4 + tr];
#pragma unroll
        for (int nf = 0; nf < 4; nf++) {
            const int dn = ng * 32 + nf * 8 + tq;
            uint32_t b0 = VT[dn * PV_LD + kb + tr];
            uint32_t b1 = VT[dn * PV_LD + kb + 4 + tr];
            MMA_TF32(o[nf], a0, a1, a2, a3, b0, b1);
        }
    }

    // ---- store O -> g_attn [B*N, 768] ----
#pragma unroll
    for (int nf = 0; nf < 4; nf++) {
        const int d0 = ng * 32 + nf * 8 + 2 * tr;
        if (i0 < NTOK) {
            float2 v = make_float2(o[nf][0], o[nf][1]);
            *(float2*)(attn_out + (size_t)(b * NTOK + i0) * DIM + h * HDIM + d0) = v;
        }
        if (i1 < NTOK) {
            float2 v = make_float2(o[nf][2], o[nf][3]);
            *(float2*)(attn_out + (size_t)(b * NTOK + i1) * DIM + h * HDIM + d0) = v;
        }
    }
}

// ---------------------------------------------------------------------------
// Launch
// ---------------------------------------------------------------------------
extern "C" void kernel_launch(void* const* d_in, const int* in_sizes, int n_in,
                              void* d_out, int out_size)
{
    const float* x      = (const float*)d_in[0];
    const float* scale  = (const float*)d_in[1];
    const float* w_qkv  = (const float*)d_in[2];
    const float* w_proj = (const float*)d_in[3];
    const float* b_proj = (const float*)d_in[4];
    float* out = (float*)d_out;

    float* qkv_ptr = nullptr;
    float* attn_ptr = nullptr;
    cudaGetSymbolAddress((void**)&qkv_ptr, g_qkv);
    cudaGetSymbolAddress((void**)&attn_ptr, g_attn);

    // 1) QKV projection (tf32 TC)
    {
        dim3 grid(KQKV / 128, (MROWS + 127) / 128);
        gemm_tf32_kernel<0><<<grid, 256>>>(x, w_qkv, qkv_ptr,
                                           MROWS, KQKV, DIM, nullptr, nullptr);
    }

    // 2) Tensor-core masked attention
    {
        size_t smem = (size_t)ATTN2_SMEM_WORDS * sizeof(uint32_t);
        cudaFuncSetAttribute(attn_mma_kernel,
                             cudaFuncAttributeMaxDynamicSharedMemorySize,
                             (int)smem);
        dim3 grid(BATCH * NHEAD, (NTOK + QT - 1) / QT);
        attn_mma_kernel<<<grid, 256, smem>>>(qkv_ptr, scale, attn_ptr);
    }

    // 3) Output projection + bias + residual (tf32 TC)
    {
        dim3 grid(DIM / 128, (MROWS + 127) / 128);
        gemm_tf32_kernel<1><<<grid, 256>>>(attn_ptr, w_proj, out,
                                           MROWS, DIM, DIM, b_proj, x);
    }
}

// round 9
// speedup vs baseline: 2.4633x; 1.1879x over previous
#include <cuda_runtime.h>
#include <math.h>
#include <stdint.h>

// Problem constants
#define BATCH   64
#define NTOK    197
#define DIM     768
#define NHEAD   12
#define HDIM    64
#define MROWS   (BATCH * NTOK)     // 12608
#define KQKV    (3 * DIM)          // 2304

// Scratch (device globals — no allocation allowed)
__device__ float g_qkv[(size_t)MROWS * KQKV];   // [M, 2304] row-major
__device__ float g_attn[(size_t)MROWS * DIM];   // [M, 768]  row-major

// ---------------------------------------------------------------------------
// tf32 mma helpers
// ---------------------------------------------------------------------------
#define MMA_TF32(c, a0, a1, a2, a3, b0, b1)                                  \
    asm volatile(                                                            \
        "mma.sync.aligned.m16n8k8.row.col.f32.tf32.tf32.f32 "                \
        "{%0,%1,%2,%3},{%4,%5,%6,%7},{%8,%9},{%0,%1,%2,%3};"                 \
        : "+f"(c[0]), "+f"(c[1]), "+f"(c[2]), "+f"(c[3])                     \
        : "r"(a0), "r"(a1), "r"(a2), "r"(a3), "r"(b0), "r"(b1))

__device__ __forceinline__ uint32_t f2tf32(float x) {
    uint32_t u;
    asm("cvt.rna.tf32.f32 %0, %1;" : "=r"(u) : "f"(x));
    return u;
}

__device__ __forceinline__ void cp16(uint32_t dst, const void* src, int sz) {
    asm volatile("cp.async.cg.shared.global [%0], [%1], 16, %2;"
                 :: "r"(dst), "l"(src), "r"(sz));
}
__device__ __forceinline__ void cp_commit() {
    asm volatile("cp.async.commit_group;");
}

// ---------------------------------------------------------------------------
// TF32 TC GEMM (NT), cp.async 3-stage pipeline. Raw fp32 bits fed to mma
// (HW tf32 truncation). C[m,n] = sum_k A[m,k]*B[n,k].
// BM=BN=128, BK=16, 256 threads, warp tile 64x32. EPI1: +bias[n]+resid.
// ---------------------------------------------------------------------------
#define G_LDSW 20                       // row stride words; tq*20+tr distinct mod 32
#define G_STW  ((128 + 128) * G_LDSW)   // 5120 words per stage
#define G_SMEM_BYTES (3 * G_STW * 4)    // 61440

template <int EPI>
__global__ __launch_bounds__(256, 2)
void gemm_tf32_kernel(const float* __restrict__ A,
                      const float* __restrict__ Bw,
                      float* __restrict__ C,
                      int M, int Nn, int K,
                      const float* __restrict__ bias,
                      const float* __restrict__ resid)
{
    extern __shared__ uint32_t smg[];

    const int tid  = threadIdx.x;
    const int warp = tid >> 5, lane = tid & 31;
    const int wm = warp & 1;
    const int wn = warp >> 1;
    const int tq = lane >> 2;
    const int tr = lane & 3;
    const int m0 = blockIdx.y * 128;
    const int n0 = blockIdx.x * 128;

    const int lrow = tid >> 1;
    const int lcol = (tid & 1) * 8;

    const uint32_t sb = (uint32_t)__cvta_generic_to_shared(smg);
    const float* aptr = A + (size_t)(m0 + lrow) * K + lcol;
    const float* bptr = Bw + (size_t)(n0 + lrow) * K + lcol;
    const int asz = (m0 + lrow < M) ? 16 : 0;
    const uint32_t da0 = sb + (uint32_t)(lrow * G_LDSW + lcol) * 4;
    const uint32_t db0 = da0 + 128 * G_LDSW * 4;

    float c[4][4][4];
#pragma unroll
    for (int mt = 0; mt < 4; mt++)
#pragma unroll
        for (int nt = 0; nt < 4; nt++)
#pragma unroll
            for (int i = 0; i < 4; i++) c[mt][nt][i] = 0.f;

    const int nit = K / 16;

    // prologue: stages 0,1
#pragma unroll
    for (int s = 0; s < 2; s++) {
        const int k0 = s * 16;
        cp16(da0 + s * G_STW * 4,      aptr + k0,     asz);
        cp16(da0 + s * G_STW * 4 + 16, aptr + k0 + 4, asz);
        cp16(db0 + s * G_STW * 4,      bptr + k0,     16);
        cp16(db0 + s * G_STW * 4 + 16, bptr + k0 + 4, 16);
        cp_commit();
    }

    int cur = 0;
    for (int it = 0; it < nit; it++) {
        if (it + 2 < nit) { asm volatile("cp.async.wait_group 1;"); }
        else              { asm volatile("cp.async.wait_group 0;"); }
        __syncthreads();

        // issue stage it+2 (overwrites stage computed at it-1; sync above guards)
        if (it + 2 < nit) {
            int s = cur + 2; if (s >= 3) s -= 3;
            const int k0 = (it + 2) * 16;
            cp16(da0 + s * G_STW * 4,      aptr + k0,     asz);
            cp16(da0 + s * G_STW * 4 + 16, aptr + k0 + 4, asz);
            cp16(db0 + s * G_STW * 4,      bptr + k0,     16);
            cp16(db0 + s * G_STW * 4 + 16, bptr + k0 + 4, 16);
            cp_commit();
        }

        const uint32_t* As = smg + cur * G_STW;
        const uint32_t* Bs = As + 128 * G_LDSW;
#pragma unroll
        for (int ks = 0; ks < 16; ks += 8) {
            uint32_t af[4][4], bf[4][2];
#pragma unroll
            for (int mt = 0; mt < 4; mt++) {
                const int rb = wm * 64 + mt * 16;
                af[mt][0] = As[(rb + tq) * G_LDSW + ks + tr];
                af[mt][1] = As[(rb + 8 + tq) * G_LDSW + ks + tr];
                af[mt][2] = As[(rb + tq) * G_LDSW + ks + 4 + tr];
                af[mt][3] = As[(rb + 8 + tq) * G_LDSW + ks + 4 + tr];
            }
#pragma unroll
            for (int nt = 0; nt < 4; nt++) {
                const int cb = wn * 32 + nt * 8 + tq;
                bf[nt][0] = Bs[cb * G_LDSW + ks + tr];
                bf[nt][1] = Bs[cb * G_LDSW + ks + 4 + tr];
            }
#pragma unroll
            for (int mt = 0; mt < 4; mt++)
#pragma unroll
                for (int nt = 0; nt < 4; nt++)
                    MMA_TF32(c[mt][nt], af[mt][0], af[mt][1], af[mt][2], af[mt][3],
                             bf[nt][0], bf[nt][1]);
        }
        cur++; if (cur == 3) cur = 0;
    }

    // epilogue
#pragma unroll
    for (int mt = 0; mt < 4; mt++) {
        const int r0 = m0 + wm * 64 + mt * 16 + tq;
        const int r1 = r0 + 8;
#pragma unroll
        for (int nt = 0; nt < 4; nt++) {
            const int gn = n0 + wn * 32 + nt * 8 + 2 * tr;
            float2 bb = make_float2(0.f, 0.f);
            if (EPI == 1) bb = *(const float2*)(bias + gn);
            if (r0 < M) {
                float2 v = make_float2(c[mt][nt][0], c[mt][nt][1]);
                if (EPI == 1) {
                    float2 rr = *(const float2*)(resid + (size_t)r0 * Nn + gn);
                    v.x += bb.x + rr.x; v.y += bb.y + rr.y;
                }
                *(float2*)(C + (size_t)r0 * Nn + gn) = v;
            }
            if (r1 < M) {
                float2 v = make_float2(c[mt][nt][2], c[mt][nt][3]);
                if (EPI == 1) {
                    float2 rr = *(const float2*)(resid + (size_t)r1 * Nn + gn);
                    v.x += bb.x + rr.x; v.y += bb.y + rr.y;
                }
                *(float2*)(C + (size_t)r1 * Nn + gn) = v;
            }
        }
    }
}

// ---------------------------------------------------------------------------
// Tensor-core attention, 512 threads (16 warps). Block = (b,h,qtile 64).
// warp = (mf = q-frag 0..3, ng = quarter 0..3). S: keys split 4x56.
// O: dims split 4x16. P overlays the dead K tile.
// ---------------------------------------------------------------------------
#define QT    64
#define NKPAD 224
#define QK_LD 68     // (tq*68+tr) mod 32 distinct -> conflict-free
#define PV_LD 233    // 4*233 % 32 == 4 -> 2-way VT-fill STS; frag reads near-clean

#define QS_OFF   0
#define KS_OFF   (QS_OFF + QT * QK_LD)          // 4352
#define VT_OFF   (KS_OFF + NKPAD * QK_LD)       // 19584
#define PMAX_OFF (VT_OFF + HDIM * PV_LD)        // 34496
#define PSUM_OFF (PMAX_OFF + 4 * QT)            // 34752
#define ATTN2_SMEM_WORDS (PSUM_OFF + 4 * QT)    // 35008 w = 140032 B

__global__ __launch_bounds__(512, 1)
void attn_mma_kernel(const float* __restrict__ qkv,
                     const float* __restrict__ scale,
                     float* __restrict__ attn_out)
{
    extern __shared__ uint32_t smw[];
    uint32_t* Qs = smw + QS_OFF;
    uint32_t* Ks = smw + KS_OFF;
    uint32_t* VT = smw + VT_OFF;
    uint32_t* Pu = smw + KS_OFF;               // overlay, written after Ks dead
    float* pmax  = (float*)(smw + PMAX_OFF);
    float* psum  = (float*)(smw + PSUM_OFF);

    const int bh = blockIdx.x;
    const int b = bh / NHEAD, h = bh % NHEAD;
    const int q0 = blockIdx.y * QT;
    const int tid = threadIdx.x;
    const int warp = tid >> 5, lane = tid & 31;
    const int tq = lane >> 2, tr = lane & 3;
    const int mf = warp & 3;          // q-frag (16 rows)
    const int ng = warp >> 2;         // quarter (keys / dims)
    const float sc = scale[h];

    // ---- load Q (scaled), K into smem as tf32; zero VT pad cols ----
    for (int idx = tid; idx < QT * 16; idx += 512) {
        int r = idx >> 4, c4 = (idx & 15) * 4;
        int q = q0 + r;
        if (q < NTOK) {
            float4 v = *(const float4*)(qkv + (size_t)(b * NTOK + q) * KQKV + h * HDIM + c4);
            uint32_t* p = &Qs[r * QK_LD + c4];
            p[0] = f2tf32(v.x * sc); p[1] = f2tf32(v.y * sc);
            p[2] = f2tf32(v.z * sc); p[3] = f2tf32(v.w * sc);
        }
    }
    for (int idx = tid; idx < NTOK * 16; idx += 512) {
        int j = idx >> 4, c4 = (idx & 15) * 4;
        float4 v = *(const float4*)(qkv + (size_t)(b * NTOK + j) * KQKV + DIM + h * HDIM + c4);
        uint32_t* p = &Ks[j * QK_LD + c4];
        p[0] = f2tf32(v.x); p[1] = f2tf32(v.y);
        p[2] = f2tf32(v.z); p[3] = f2tf32(v.w);
    }
    for (int idx = tid; idx < HDIM * 28; idx += 512) {   // keys 196..223 pad -> 0
        int d = idx / 28, j = 196 + idx % 28;
        VT[d * PV_LD + j] = 0;
    }
    __syncthreads();
    for (int idx = tid; idx < NTOK * 16; idx += 512) {   // V -> VT transpose
        int j = idx >> 4, c4 = (idx & 15) * 4;
        float4 v = *(const float4*)(qkv + (size_t)(b * NTOK + j) * KQKV + 2 * DIM + h * HDIM + c4);
        VT[(c4 + 0) * PV_LD + j] = f2tf32(v.x);
        VT[(c4 + 1) * PV_LD + j] = f2tf32(v.y);
        VT[(c4 + 2) * PV_LD + j] = f2tf32(v.z);
        VT[(c4 + 3) * PV_LD + j] = f2tf32(v.w);
    }
    __syncthreads();

    // ---- S = Q K^T : warp covers keys [ng*56, ng*56+56) = 7 frags ----
    float c[7][4];
#pragma unroll
    for (int nf = 0; nf < 7; nf++)
#pragma unroll
        for (int i = 0; i < 4; i++) c[nf][i] = 0.f;

#pragma unroll
    for (int ks = 0; ks < 8; ks++) {
        const int kb = ks * 8;
        uint32_t a0 = Qs[(mf * 16 + tq) * QK_LD + kb + tr];
        uint32_t a1 = Qs[(mf * 16 + 8 + tq) * QK_LD + kb + tr];
        uint32_t a2 = Qs[(mf * 16 + tq) * QK_LD + kb + 4 + tr];
        uint32_t a3 = Qs[(mf * 16 + 8 + tq) * QK_LD + kb + 4 + tr];
#pragma unroll
        for (int nf = 0; nf < 7; nf++) {
            const int kn = ng * 56 + nf * 8 + tq;
            uint32_t b0 = Ks[kn * QK_LD + kb + tr];
            uint32_t b1 = Ks[kn * QK_LD + kb + 4 + tr];
            MMA_TF32(c[nf], a0, a1, a2, a3, b0, b1);
        }
    }

    // ---- mask + quarter-max ----
    const int i0 = q0 + mf * 16 + tq;
    const int i1 = i0 + 8;
    float mx0 = -INFINITY, mx1 = -INFINITY;
#pragma unroll
    for (int nf = 0; nf < 7; nf++) {
        const int j0 = ng * 56 + nf * 8 + 2 * tr;
        const int j1 = j0 + 1;
        c[nf][0] = (j0 >= NTOK || j0 == i0) ? -INFINITY : c[nf][0];
        c[nf][1] = (j1 >= NTOK || j1 == i0) ? -INFINITY : c[nf][1];
        c[nf][2] = (j0 >= NTOK || j0 == i1) ? -INFINITY : c[nf][2];
        c[nf][3] = (j1 >= NTOK || j1 == i1) ? -INFINITY : c[nf][3];
        mx0 = fmaxf(mx0, fmaxf(c[nf][0], c[nf][1]));
        mx1 = fmaxf(mx1, fmaxf(c[nf][2], c[nf][3]));
    }
    mx0 = fmaxf(mx0, __shfl_xor_sync(0xFFFFFFFFu, mx0, 1));
    mx0 = fmaxf(mx0, __shfl_xor_sync(0xFFFFFFFFu, mx0, 2));
    mx1 = fmaxf(mx1, __shfl_xor_sync(0xFFFFFFFFu, mx1, 1));
    mx1 = fmaxf(mx1, __shfl_xor_sync(0xFFFFFFFFu, mx1, 2));
    if (tr == 0) {
        pmax[ng * QT + mf * 16 + tq]     = mx0;
        pmax[ng * QT + mf * 16 + tq + 8] = mx1;
    }
    __syncthreads();
    const int row0 = mf * 16 + tq;
    const float M0 = fmaxf(fmaxf(pmax[row0],          pmax[QT + row0]),
                           fmaxf(pmax[2 * QT + row0], pmax[3 * QT + row0]));
    const float M1 = fmaxf(fmaxf(pmax[row0 + 8],          pmax[QT + row0 + 8]),
                           fmaxf(pmax[2 * QT + row0 + 8], pmax[3 * QT + row0 + 8]));

    // ---- exp + quarter-sum ----
    float s0 = 0.f, s1 = 0.f;
#pragma unroll
    for (int nf = 0; nf < 7; nf++) {
        c[nf][0] = __expf(c[nf][0] - M0);
        c[nf][1] = __expf(c[nf][1] - M0);
        c[nf][2] = __expf(c[nf][2] - M1);
        c[nf][3] = __expf(c[nf][3] - M1);
        s0 += c[nf][0] + c[nf][1];
        s1 += c[nf][2] + c[nf][3];
    }
    s0 += __shfl_xor_sync(0xFFFFFFFFu, s0, 1);
    s0 += __shfl_xor_sync(0xFFFFFFFFu, s0, 2);
    s1 += __shfl_xor_sync(0xFFFFFFFFu, s1, 1);
    s1 += __shfl_xor_sync(0xFFFFFFFFu, s1, 2);
    if (tr == 0) {
        psum[ng * QT + row0]     = s0;
        psum[ng * QT + row0 + 8] = s1;
    }
    __syncthreads();   // all S-reads of Ks complete -> P overlay safe
    const float inv0 = 1.f / (psum[row0] + psum[QT + row0] +
                              psum[2 * QT + row0] + psum[3 * QT + row0]);
    const float inv1 = 1.f / (psum[row0 + 8] + psum[QT + row0 + 8] +
                              psum[2 * QT + row0 + 8] + psum[3 * QT + row0 + 8]);

    // ---- write P (tf32, normalized) into overlay ----
#pragma unroll
    for (int nf = 0; nf < 7; nf++) {
        const int col = ng * 56 + nf * 8 + 2 * tr;
        Pu[(mf * 16 + tq) * PV_LD + col]         = f2tf32(c[nf][0] * inv0);
        Pu[(mf * 16 + tq) * PV_LD + col + 1]     = f2tf32(c[nf][1] * inv0);
        Pu[(mf * 16 + 8 + tq) * PV_LD + col]     = f2tf32(c[nf][2] * inv1);
        Pu[(mf * 16 + 8 + tq) * PV_LD + col + 1] = f2tf32(c[nf][3] * inv1);
    }
    __syncthreads();

    // ---- O = P V^T : warp covers dims [ng*16, ng*16+16) = 2 frags ----
    float o[2][4];
#pragma unroll
    for (int nf = 0; nf < 2; nf++)
#pragma unroll
        for (int i = 0; i < 4; i++) o[nf][i] = 0.f;

#pragma unroll
    for (int kc = 0; kc < 28; kc++) {
        const int kb = kc * 8;
        uint32_t a0 = Pu[(mf * 16 + tq) * PV_LD + kb + tr];
        uint32_t a1 = Pu[(mf * 16 + 8 + tq) * PV_LD + kb + tr];
        uint32_t a2 = Pu[(mf * 16 + tq) * PV_LD + kb + 4 + tr];
        uint32_t a3 = Pu[(mf * 16 + 8 + tq) * PV_LD + kb + 4 + tr];
#pragma unroll
        for (int nf = 0; nf < 2; nf++) {
            const int dn = ng * 16 + nf * 8 + tq;
            uint32_t b0 = VT[dn * PV_LD + kb + tr];
            uint32_t b1 = VT[dn * PV_LD + kb + 4 + tr];
            MMA_TF32(o[nf], a0, a1, a2, a3, b0, b1);
        }
    }

    // ---- store O -> g_attn ----
#pragma unroll
    for (int nf = 0; nf < 2; nf++) {
        const int d0 = ng * 16 + nf * 8 + 2 * tr;
        if (i0 < NTOK) {
            float2 v = make_float2(o[nf][0], o[nf][1]);
            *(float2*)(attn_out + (size_t)(b * NTOK + i0) * DIM + h * HDIM + d0) = v;
        }
        if (i1 < NTOK) {
            float2 v = make_float2(o[nf][2], o[nf][3]);
            *(float2*)(attn_out + (size_t)(b * NTOK + i1) * DIM + h * HDIM + d0) = v;
        }
    }
}

// ---------------------------------------------------------------------------
// Launch
// ---------------------------------------------------------------------------
extern "C" void kernel_launch(void* const* d_in, const int* in_sizes, int n_in,
                              void* d_out, int out_size)
{
    const float* x      = (const float*)d_in[0];
    const float* scale  = (const float*)d_in[1];
    const float* w_qkv  = (const float*)d_in[2];
    const float* w_proj = (const float*)d_in[3];
    const float* b_proj = (const float*)d_in[4];
    float* out = (float*)d_out;

    float* qkv_ptr = nullptr;
    float* attn_ptr = nullptr;
    cudaGetSymbolAddress((void**)&qkv_ptr, g_qkv);
    cudaGetSymbolAddress((void**)&attn_ptr, g_attn);

    cudaFuncSetAttribute(gemm_tf32_kernel<0>,
                         cudaFuncAttributeMaxDynamicSharedMemorySize, G_SMEM_BYTES);
    cudaFuncSetAttribute(gemm_tf32_kernel<1>,
                         cudaFuncAttributeMaxDynamicSharedMemorySize, G_SMEM_BYTES);

    // 1) QKV projection (tf32 TC + cp.async)
    {
        dim3 grid(KQKV / 128, (MROWS + 127) / 128);
        gemm_tf32_kernel<0><<<grid, 256, G_SMEM_BYTES>>>(
            x, w_qkv, qkv_ptr, MROWS, KQKV, DIM, nullptr, nullptr);
    }

    // 2) Tensor-core masked attention (512 threads)
    {
        size_t smem = (size_t)ATTN2_SMEM_WORDS * sizeof(uint32_t);
        cudaFuncSetAttribute(attn_mma_kernel,
                             cudaFuncAttributeMaxDynamicSharedMemorySize,
                             (int)smem);
        dim3 grid(BATCH * NHEAD, (NTOK + QT - 1) / QT);
        attn_mma_kernel<<<grid, 512, smem>>>(qkv_ptr, scale, attn_ptr);
    }

    // 3) Output projection + bias + residual (tf32 TC + cp.async)
    {
        dim3 grid(DIM / 128, (MROWS + 127) / 128);
        gemm_tf32_kernel<1><<<grid, 256, G_SMEM_BYTES>>>(
            attn_ptr, w_proj, out, MROWS, DIM, DIM, b_proj, x);
    }
}

// round 10
// speedup vs baseline: 2.5701x; 1.0434x over previous
#include <cuda_runtime.h>
#include <math.h>
#include <stdint.h>

// Problem constants
#define BATCH   64
#define NTOK    197
#define DIM     768
#define NHEAD   12
#define HDIM    64
#define MROWS   (BATCH * NTOK)     // 12608
#define KQKV    (3 * DIM)          // 2304

// Scratch (device globals — no allocation allowed)
__device__ float g_qkv[(size_t)MROWS * KQKV];   // [M, 2304] row-major
__device__ float g_attn[(size_t)MROWS * DIM];   // [M, 768]  row-major

// ---------------------------------------------------------------------------
// tf32 mma helpers
// ---------------------------------------------------------------------------
#define MMA_TF32(c, a0, a1, a2, a3, b0, b1)                                  \
    asm volatile(                                                            \
        "mma.sync.aligned.m16n8k8.row.col.f32.tf32.tf32.f32 "                \
        "{%0,%1,%2,%3},{%4,%5,%6,%7},{%8,%9},{%0,%1,%2,%3};"                 \
        : "+f"(c[0]), "+f"(c[1]), "+f"(c[2]), "+f"(c[3])                     \
        : "r"(a0), "r"(a1), "r"(a2), "r"(a3), "r"(b0), "r"(b1))

__device__ __forceinline__ uint32_t f2tf32(float x) {
    uint32_t u;
    asm("cvt.rna.tf32.f32 %0, %1;" : "=r"(u) : "f"(x));
    return u;
}

__device__ __forceinline__ void cp16(uint32_t dst, const void* src, int sz) {
    asm volatile("cp.async.cg.shared.global [%0], [%1], 16, %2;"
                 :: "r"(dst), "l"(src), "r"(sz));
}
__device__ __forceinline__ void cp_commit() {
    asm volatile("cp.async.commit_group;");
}

// ---------------------------------------------------------------------------
// TF32 TC GEMM (NT), cp.async 3-stage, BK=32. Raw fp32 bits to mma.
// C[m,n] = sum_k A[m,k]*B[n,k]. 256 thr, warp tile 64x32. EPI1: +bias+resid.
// ---------------------------------------------------------------------------
#define G_BK   32
#define G_LDSW 36                        // (tq*36+tr) -> 4tq+tr distinct mod 32
#define G_STW  ((128 + 128) * G_LDSW)    // 9216 words per stage
#define G_SMEM_BYTES (3 * G_STW * 4)     // 110592

template <int EPI>
__global__ __launch_bounds__(256, 2)
void gemm_tf32_kernel(const float* __restrict__ A,
                      const float* __restrict__ Bw,
                      float* __restrict__ C,
                      int M, int Nn, int K,
                      const float* __restrict__ bias,
                      const float* __restrict__ resid)
{
    extern __shared__ uint32_t smg[];

    const int tid  = threadIdx.x;
    const int warp = tid >> 5, lane = tid & 31;
    const int wm = warp & 1;
    const int wn = warp >> 1;
    const int tq = lane >> 2;
    const int tr = lane & 3;
    const int m0 = blockIdx.y * 128;
    const int n0 = blockIdx.x * 128;

    const int lrow = tid >> 1;            // 0..127
    const int lcol = (tid & 1) * 16;      // 0 or 16 (each thread: 16 floats)

    const uint32_t sb = (uint32_t)__cvta_generic_to_shared(smg);
    const float* aptr = A + (size_t)(m0 + lrow) * K + lcol;
    const float* bptr = Bw + (size_t)(n0 + lrow) * K + lcol;
    const int asz = (m0 + lrow < M) ? 16 : 0;
    const uint32_t da0 = sb + (uint32_t)(lrow * G_LDSW + lcol) * 4;
    const uint32_t db0 = da0 + 128 * G_LDSW * 4;

    float c[4][4][4];
#pragma unroll
    for (int mt = 0; mt < 4; mt++)
#pragma unroll
        for (int nt = 0; nt < 4; nt++)
#pragma unroll
            for (int i = 0; i < 4; i++) c[mt][nt][i] = 0.f;

    const int nit = K / G_BK;

    // prologue: stages 0,1
#pragma unroll
    for (int s = 0; s < 2; s++) {
        const int k0 = s * G_BK;
#pragma unroll
        for (int q = 0; q < 4; q++) {
            cp16(da0 + s * G_STW * 4 + q * 16, aptr + k0 + q * 4, asz);
            cp16(db0 + s * G_STW * 4 + q * 16, bptr + k0 + q * 4, 16);
        }
        cp_commit();
    }

    int cur = 0;
    for (int it = 0; it < nit; it++) {
        if (it + 2 < nit) { asm volatile("cp.async.wait_group 1;"); }
        else              { asm volatile("cp.async.wait_group 0;"); }
        __syncthreads();

        if (it + 2 < nit) {
            int s = cur + 2; if (s >= 3) s -= 3;
            const int k0 = (it + 2) * G_BK;
#pragma unroll
            for (int q = 0; q < 4; q++) {
                cp16(da0 + s * G_STW * 4 + q * 16, aptr + k0 + q * 4, asz);
                cp16(db0 + s * G_STW * 4 + q * 16, bptr + k0 + q * 4, 16);
            }
            cp_commit();
        }

        const uint32_t* As = smg + cur * G_STW;
        const uint32_t* Bs = As + 128 * G_LDSW;
#pragma unroll
        for (int ks = 0; ks < G_BK; ks += 8) {
            uint32_t af[4][4], bf[4][2];
#pragma unroll
            for (int mt = 0; mt < 4; mt++) {
                const int rb = wm * 64 + mt * 16;
                af[mt][0] = As[(rb + tq) * G_LDSW + ks + tr];
                af[mt][1] = As[(rb + 8 + tq) * G_LDSW + ks + tr];
                af[mt][2] = As[(rb + tq) * G_LDSW + ks + 4 + tr];
                af[mt][3] = As[(rb + 8 + tq) * G_LDSW + ks + 4 + tr];
            }
#pragma unroll
            for (int nt = 0; nt < 4; nt++) {
                const int cb = wn * 32 + nt * 8 + tq;
                bf[nt][0] = Bs[cb * G_LDSW + ks + tr];
                bf[nt][1] = Bs[cb * G_LDSW + ks + 4 + tr];
            }
#pragma unroll
            for (int mt = 0; mt < 4; mt++)
#pragma unroll
                for (int nt = 0; nt < 4; nt++)
                    MMA_TF32(c[mt][nt], af[mt][0], af[mt][1], af[mt][2], af[mt][3],
                             bf[nt][0], bf[nt][1]);
        }
        cur++; if (cur == 3) cur = 0;
    }

    // epilogue
#pragma unroll
    for (int mt = 0; mt < 4; mt++) {
        const int r0 = m0 + wm * 64 + mt * 16 + tq;
        const int r1 = r0 + 8;
#pragma unroll
        for (int nt = 0; nt < 4; nt++) {
            const int gn = n0 + wn * 32 + nt * 8 + 2 * tr;
            float2 bb = make_float2(0.f, 0.f);
            if (EPI == 1) bb = *(const float2*)(bias + gn);
            if (r0 < M) {
                float2 v = make_float2(c[mt][nt][0], c[mt][nt][1]);
                if (EPI == 1) {
                    float2 rr = *(const float2*)(resid + (size_t)r0 * Nn + gn);
                    v.x += bb.x + rr.x; v.y += bb.y + rr.y;
                }
                *(float2*)(C + (size_t)r0 * Nn + gn) = v;
            }
            if (r1 < M) {
                float2 v = make_float2(c[mt][nt][2], c[mt][nt][3]);
                if (EPI == 1) {
                    float2 rr = *(const float2*)(resid + (size_t)r1 * Nn + gn);
                    v.x += bb.x + rr.x; v.y += bb.y + rr.y;
                }
                *(float2*)(C + (size_t)r1 * Nn + gn) = v;
            }
        }
    }
}

// ---------------------------------------------------------------------------
// Tensor-core attention, 512 threads. Block = (b,h); K/V loaded ONCE,
// q-tiles (4 x 64) looped inside. warp = (mf q-frag, ng quarter).
// S: keys split 4x56. O: dims split 4x16. P in its own region (no overlay).
// ---------------------------------------------------------------------------
#define QT    64
#define NKPAD 224
#define QK_LD 68
#define PV_LD 233

#define QS_OFF   0
#define KS_OFF   (QS_OFF + QT * QK_LD)          // 4352
#define VT_OFF   (KS_OFF + NKPAD * QK_LD)       // 19584
#define PU_OFF   (VT_OFF + HDIM * PV_LD)        // 34496
#define PMAX_OFF (PU_OFF + QT * PV_LD)          // 49408
#define PSUM_OFF (PMAX_OFF + 4 * QT)            // 49664
#define ATTN2_SMEM_WORDS (PSUM_OFF + 4 * QT)    // 49920 w = 199680 B

__global__ __launch_bounds__(512, 1)
void attn_mma_kernel(const float* __restrict__ qkv,
                     const float* __restrict__ scale,
                     float* __restrict__ attn_out)
{
    extern __shared__ uint32_t smw[];
    uint32_t* Qs = smw + QS_OFF;
    uint32_t* Ks = smw + KS_OFF;
    uint32_t* VT = smw + VT_OFF;
    uint32_t* Pu = smw + PU_OFF;
    float* pmax  = (float*)(smw + PMAX_OFF);
    float* psum  = (float*)(smw + PSUM_OFF);

    const int bh = blockIdx.x;
    const int b = bh / NHEAD, h = bh % NHEAD;
    const int tid = threadIdx.x;
    const int warp = tid >> 5, lane = tid & 31;
    const int tq = lane >> 2, tr = lane & 3;
    const int mf = warp & 3;
    const int ng = warp >> 2;
    const float sc = scale[h];

    // ---- load K, VT once per (b,h) ----
    for (int idx = tid; idx < NTOK * 16; idx += 512) {
        int j = idx >> 4, c4 = (idx & 15) * 4;
        float4 v = *(const float4*)(qkv + (size_t)(b * NTOK + j) * KQKV + DIM + h * HDIM + c4);
        uint32_t* p = &Ks[j * QK_LD + c4];
        p[0] = f2tf32(v.x); p[1] = f2tf32(v.y);
        p[2] = f2tf32(v.z); p[3] = f2tf32(v.w);
    }
    for (int idx = tid; idx < HDIM * 28; idx += 512) {   // VT pad keys 196..223
        int d = idx / 28, j = 196 + idx % 28;
        VT[d * PV_LD + j] = 0;
    }
    __syncthreads();
    for (int idx = tid; idx < NTOK * 16; idx += 512) {   // V -> VT transpose
        int j = idx >> 4, c4 = (idx & 15) * 4;
        float4 v = *(const float4*)(qkv + (size_t)(b * NTOK + j) * KQKV + 2 * DIM + h * HDIM + c4);
        VT[(c4 + 0) * PV_LD + j] = f2tf32(v.x);
        VT[(c4 + 1) * PV_LD + j] = f2tf32(v.y);
        VT[(c4 + 2) * PV_LD + j] = f2tf32(v.z);
        VT[(c4 + 3) * PV_LD + j] = f2tf32(v.w);
    }

    const int row0 = mf * 16 + tq;

    for (int qt = 0; qt < 4; qt++) {
        const int q0 = qt * QT;

        // ---- load Q tile (scaled) ----
        for (int idx = tid; idx < QT * 16; idx += 512) {
            int r = idx >> 4, c4 = (idx & 15) * 4;
            int q = q0 + r;
            if (q < NTOK) {
                float4 v = *(const float4*)(qkv + (size_t)(b * NTOK + q) * KQKV + h * HDIM + c4);
                uint32_t* p = &Qs[r * QK_LD + c4];
                p[0] = f2tf32(v.x * sc); p[1] = f2tf32(v.y * sc);
                p[2] = f2tf32(v.z * sc); p[3] = f2tf32(v.w * sc);
            }
        }
        __syncthreads();   // Q (and first iter: K/VT) visible

        // ---- S = Q K^T : 7 key-frags for this warp's quarter ----
        float c[7][4];
#pragma unroll
        for (int nf = 0; nf < 7; nf++)
#pragma unroll
            for (int i = 0; i < 4; i++) c[nf][i] = 0.f;

#pragma unroll
        for (int ks = 0; ks < 8; ks++) {
            const int kb = ks * 8;
            uint32_t a0 = Qs[(mf * 16 + tq) * QK_LD + kb + tr];
            uint32_t a1 = Qs[(mf * 16 + 8 + tq) * QK_LD + kb + tr];
            uint32_t a2 = Qs[(mf * 16 + tq) * QK_LD + kb + 4 + tr];
            uint32_t a3 = Qs[(mf * 16 + 8 + tq) * QK_LD + kb + 4 + tr];
#pragma unroll
            for (int nf = 0; nf < 7; nf++) {
                const int kn = ng * 56 + nf * 8 + tq;
                uint32_t b0 = Ks[kn * QK_LD + kb + tr];
                uint32_t b1 = Ks[kn * QK_LD + kb + 4 + tr];
                MMA_TF32(c[nf], a0, a1, a2, a3, b0, b1);
            }
        }

        // ---- mask + quarter-max ----
        const int i0 = q0 + mf * 16 + tq;
        const int i1 = i0 + 8;
        float mx0 = -INFINITY, mx1 = -INFINITY;
#pragma unroll
        for (int nf = 0; nf < 7; nf++) {
            const int j0 = ng * 56 + nf * 8 + 2 * tr;
            const int j1 = j0 + 1;
            c[nf][0] = (j0 >= NTOK || j0 == i0) ? -INFINITY : c[nf][0];
            c[nf][1] = (j1 >= NTOK || j1 == i0) ? -INFINITY : c[nf][1];
            c[nf][2] = (j0 >= NTOK || j0 == i1) ? -INFINITY : c[nf][2];
            c[nf][3] = (j1 >= NTOK || j1 == i1) ? -INFINITY : c[nf][3];
            mx0 = fmaxf(mx0, fmaxf(c[nf][0], c[nf][1]));
            mx1 = fmaxf(mx1, fmaxf(c[nf][2], c[nf][3]));
        }
        mx0 = fmaxf(mx0, __shfl_xor_sync(0xFFFFFFFFu, mx0, 1));
        mx0 = fmaxf(mx0, __shfl_xor_sync(0xFFFFFFFFu, mx0, 2));
        mx1 = fmaxf(mx1, __shfl_xor_sync(0xFFFFFFFFu, mx1, 1));
        mx1 = fmaxf(mx1, __shfl_xor_sync(0xFFFFFFFFu, mx1, 2));
        if (tr == 0) {
            pmax[ng * QT + row0]     = mx0;
            pmax[ng * QT + row0 + 8] = mx1;
        }
        __syncthreads();
        const float M0 = fmaxf(fmaxf(pmax[row0],          pmax[QT + row0]),
                               fmaxf(pmax[2 * QT + row0], pmax[3 * QT + row0]));
        const float M1 = fmaxf(fmaxf(pmax[row0 + 8],          pmax[QT + row0 + 8]),
                               fmaxf(pmax[2 * QT + row0 + 8], pmax[3 * QT + row0 + 8]));

        // ---- exp + quarter-sum ----
        float s0 = 0.f, s1 = 0.f;
#pragma unroll
        for (int nf = 0; nf < 7; nf++) {
            c[nf][0] = __expf(c[nf][0] - M0);
            c[nf][1] = __expf(c[nf][1] - M0);
            c[nf][2] = __expf(c[nf][2] - M1);
            c[nf][3] = __expf(c[nf][3] - M1);
            s0 += c[nf][0] + c[nf][1];
            s1 += c[nf][2] + c[nf][3];
        }
        s0 += __shfl_xor_sync(0xFFFFFFFFu, s0, 1);
        s0 += __shfl_xor_sync(0xFFFFFFFFu, s0, 2);
        s1 += __shfl_xor_sync(0xFFFFFFFFu, s1, 1);
        s1 += __shfl_xor_sync(0xFFFFFFFFu, s1, 2);
        if (tr == 0) {
            psum[ng * QT + row0]     = s0;
            psum[ng * QT + row0 + 8] = s1;
        }
        __syncthreads();
        const float inv0 = 1.f / (psum[row0] + psum[QT + row0] +
                                  psum[2 * QT + row0] + psum[3 * QT + row0]);
        const float inv1 = 1.f / (psum[row0 + 8] + psum[QT + row0 + 8] +
                                  psum[2 * QT + row0 + 8] + psum[3 * QT + row0 + 8]);

        // ---- write P (tf32, normalized) ----
#pragma unroll
        for (int nf = 0; nf < 7; nf++) {
            const int col = ng * 56 + nf * 8 + 2 * tr;
            Pu[(mf * 16 + tq) * PV_LD + col]         = f2tf32(c[nf][0] * inv0);
            Pu[(mf * 16 + tq) * PV_LD + col + 1]     = f2tf32(c[nf][1] * inv0);
            Pu[(mf * 16 + 8 + tq) * PV_LD + col]     = f2tf32(c[nf][2] * inv1);
            Pu[(mf * 16 + 8 + tq) * PV_LD + col + 1] = f2tf32(c[nf][3] * inv1);
        }
        __syncthreads();

        // ---- O = P V^T : 2 dim-frags for this warp's quarter ----
        float o[2][4];
#pragma unroll
        for (int nf = 0; nf < 2; nf++)
#pragma unroll
            for (int i = 0; i < 4; i++) o[nf][i] = 0.f;

#pragma unroll
        for (int kc = 0; kc < 28; kc++) {
            const int kb = kc * 8;
            uint32_t a0 = Pu[(mf * 16 + tq) * PV_LD + kb + tr];
            uint32_t a1 = Pu[(mf * 16 + 8 + tq) * PV_LD + kb + tr];
            uint32_t a2 = Pu[(mf * 16 + tq) * PV_LD + kb + 4 + tr];
            uint32_t a3 = Pu[(mf * 16 + 8 + tq) * PV_LD + kb + 4 + tr];
#pragma unroll
            for (int nf = 0; nf < 2; nf++) {
                const int dn = ng * 16 + nf * 8 + tq;
                uint32_t b0 = VT[dn * PV_LD + kb + tr];
                uint32_t b1 = VT[dn * PV_LD + kb + 4 + tr];
                MMA_TF32(o[nf], a0, a1, a2, a3, b0, b1);
            }
        }

        // ---- store O ----
#pragma unroll
        for (int nf = 0; nf < 2; nf++) {
            const int d0 = ng * 16 + nf * 8 + 2 * tr;
            if (i0 < NTOK) {
                float2 v = make_float2(o[nf][0], o[nf][1]);
                *(float2*)(attn_out + (size_t)(b * NTOK + i0) * DIM + h * HDIM + d0) = v;
            }
            if (i1 < NTOK) {
                float2 v = make_float2(o[nf][2], o[nf][3]);
                *(float2*)(attn_out + (size_t)(b * NTOK + i1) * DIM + h * HDIM + d0) = v;
            }
        }
        __syncthreads();   // O-mma reads of Pu/Qs done before next tile rewrites
    }
}

// ---------------------------------------------------------------------------
// Launch
// ---------------------------------------------------------------------------
extern "C" void kernel_launch(void* const* d_in, const int* in_sizes, int n_in,
                              void* d_out, int out_size)
{
    const float* x      = (const float*)d_in[0];
    const float* scale  = (const float*)d_in[1];
    const float* w_qkv  = (const float*)d_in[2];
    const float* w_proj = (const float*)d_in[3];
    const float* b_proj = (const float*)d_in[4];
    float* out = (float*)d_out;

    float* qkv_ptr = nullptr;
    float* attn_ptr = nullptr;
    cudaGetSymbolAddress((void**)&qkv_ptr, g_qkv);
    cudaGetSymbolAddress((void**)&attn_ptr, g_attn);

    cudaFuncSetAttribute(gemm_tf32_kernel<0>,
                         cudaFuncAttributeMaxDynamicSharedMemorySize, G_SMEM_BYTES);
    cudaFuncSetAttribute(gemm_tf32_kernel<1>,
                         cudaFuncAttributeMaxDynamicSharedMemorySize, G_SMEM_BYTES);

    // 1) QKV projection
    {
        dim3 grid(KQKV / 128, (MROWS + 127) / 128);
        gemm_tf32_kernel<0><<<grid, 256, G_SMEM_BYTES>>>(
            x, w_qkv, qkv_ptr, MROWS, KQKV, DIM, nullptr, nullptr);
    }

    // 2) Tensor-core masked attention (KV reused across q-tiles)
    {
        size_t smem = (size_t)ATTN2_SMEM_WORDS * sizeof(uint32_t);
        cudaFuncSetAttribute(attn_mma_kernel,
                             cudaFuncAttributeMaxDynamicSharedMemorySize,
                             (int)smem);
        attn_mma_kernel<<<BATCH * NHEAD, 512, smem>>>(qkv_ptr, scale, attn_ptr);
    }

    // 3) Output projection + bias + residual
    {
        dim3 grid(DIM / 128, (MROWS + 127) / 128);
        gemm_tf32_kernel<1><<<grid, 256, G_SMEM_BYTES>>>(
            attn_ptr, w_proj, out, MROWS, DIM, DIM, b_proj, x);
    }
}

// round 11
// speedup vs baseline: 3.8666x; 1.5045x over previous
#include <cuda_runtime.h>
#include <cuda_fp16.h>
#include <math.h>
#include <stdint.h>

// Problem constants
#define BATCH   64
#define NTOK    197
#define DIM     768
#define NHEAD   12
#define HDIM    64
#define MROWS   (BATCH * NTOK)     // 12608
#define KQKV    (3 * DIM)          // 2304

// Scratch (device globals — no allocation allowed)
__device__ float  g_qkv[(size_t)MROWS * KQKV];    // fp32 qkv for attention
__device__ __half g_xh[(size_t)MROWS * DIM];      // fp16 x
__device__ __half g_wqkvh[(size_t)KQKV * DIM];    // fp16 w_qkv
__device__ __half g_wprojh[(size_t)DIM * DIM];    // fp16 w_proj
__device__ __half g_attnh[(size_t)MROWS * DIM];   // fp16 attention output

// ---------------------------------------------------------------------------
// helpers
// ---------------------------------------------------------------------------
#define MMA_TF32(c, a0, a1, a2, a3, b0, b1)                                  \
    asm volatile(                                                            \
        "mma.sync.aligned.m16n8k8.row.col.f32.tf32.tf32.f32 "                \
        "{%0,%1,%2,%3},{%4,%5,%6,%7},{%8,%9},{%0,%1,%2,%3};"                 \
        : "+f"(c[0]), "+f"(c[1]), "+f"(c[2]), "+f"(c[3])                     \
        : "r"(a0), "r"(a1), "r"(a2), "r"(a3), "r"(b0), "r"(b1))

#define MMA_F16(c, a0, a1, a2, a3, b0, b1)                                   \
    asm volatile(                                                            \
        "mma.sync.aligned.m16n8k16.row.col.f32.f16.f16.f32 "                 \
        "{%0,%1,%2,%3},{%4,%5,%6,%7},{%8,%9},{%0,%1,%2,%3};"                 \
        : "+f"(c[0]), "+f"(c[1]), "+f"(c[2]), "+f"(c[3])                     \
        : "r"(a0), "r"(a1), "r"(a2), "r"(a3), "r"(b0), "r"(b1))

#define LDSM_X4(r0, r1, r2, r3, addr)                                        \
    asm volatile("ldmatrix.sync.aligned.m8n8.x4.shared.b16 "                 \
                 "{%0,%1,%2,%3}, [%4];"                                      \
                 : "=r"(r0), "=r"(r1), "=r"(r2), "=r"(r3) : "r"(addr))

__device__ __forceinline__ uint32_t f2tf32(float x) {
    uint32_t u;
    asm("cvt.rna.tf32.f32 %0, %1;" : "=r"(u) : "f"(x));
    return u;
}

__device__ __forceinline__ void cp16(uint32_t dst, const void* src, int sz) {
    asm volatile("cp.async.cg.shared.global [%0], [%1], 16, %2;"
                 :: "r"(dst), "l"(src), "r"(sz));
}
__device__ __forceinline__ void cp_commit() {
    asm volatile("cp.async.commit_group;");
}

// ---------------------------------------------------------------------------
// fp32 -> fp16 converter (8 elems/thread)
// ---------------------------------------------------------------------------
__global__ void cvt_f2h_kernel(const float* __restrict__ in,
                               __half* __restrict__ out, int n)
{
    int i = (blockIdx.x * blockDim.x + threadIdx.x) * 8;
    if (i >= n) return;
    float4 v0 = *(const float4*)(in + i);
    float4 v1 = *(const float4*)(in + i + 4);
    __half2 h[4];
    h[0] = __floats2half2_rn(v0.x, v0.y);
    h[1] = __floats2half2_rn(v0.z, v0.w);
    h[2] = __floats2half2_rn(v1.x, v1.y);
    h[3] = __floats2half2_rn(v1.z, v1.w);
    *(uint4*)(out + i) = *(uint4*)h;
}

// ---------------------------------------------------------------------------
// FP16 TC GEMM (NT): C[m,n] = sum_k A[m,k]*B[n,k], A/B fp16, C fp32.
// BM=BN=128, BK=64, 256 thr, warp tile 64x32, cp.async 3-stage, ldmatrix.
// EPI==1: C += bias[n] + resid[m,n] (fp32).
// ---------------------------------------------------------------------------
#define GH_BK   64
#define GH_LD   72                       // halves/row (64+8 pad): LDSM conflict-free
#define GH_STH  (128 * GH_LD)            // halves per matrix per stage (9216)
#define GH_STAGE (2 * GH_STH)            // A+B halves per stage (18432)
#define GH_SMEM_BYTES (3 * GH_STAGE * 2) // 110592

template <int EPI>
__global__ __launch_bounds__(256, 2)
void gemm_f16_kernel(const __half* __restrict__ A,
                     const __half* __restrict__ Bw,
                     float* __restrict__ C,
                     int M, int Nn, int K,
                     const float* __restrict__ bias,
                     const float* __restrict__ resid)
{
    extern __shared__ __half smh[];

    const int tid  = threadIdx.x;
    const int warp = tid >> 5, lane = tid & 31;
    const int wm = warp & 1;              // m offset wm*64
    const int wn = warp >> 1;             // n offset wn*32
    const int tq = lane >> 2;
    const int tr = lane & 3;
    const int m0 = blockIdx.y * 128;
    const int n0 = blockIdx.x * 128;

    const int lrow = tid >> 1;            // 0..127
    const int lcol = (tid & 1) * 32;      // halves: 0 or 32

    const uint32_t sb = (uint32_t)__cvta_generic_to_shared(smh);
    const __half* aptr = A + (size_t)(m0 + lrow) * K + lcol;
    const __half* bptr = Bw + (size_t)(n0 + lrow) * K + lcol;
    const int asz = (m0 + lrow < M) ? 16 : 0;
    const uint32_t da0 = sb + (uint32_t)(lrow * GH_LD + lcol) * 2;
    const uint32_t db0 = da0 + GH_STH * 2;

    // ldmatrix source addresses (within a stage, relative)
    const uint32_t a_ld_off = (uint32_t)(((lane & 15)) * GH_LD + ((lane >> 4) << 3)) * 2;
    const uint32_t b_ld_off = (uint32_t)(((lane & 7) + ((lane >> 4) << 3)) * GH_LD
                                         + (((lane >> 3) & 1) << 3)) * 2;

    float c[4][4][4];
#pragma unroll
    for (int mt = 0; mt < 4; mt++)
#pragma unroll
        for (int nt = 0; nt < 4; nt++)
#pragma unroll
            for (int i = 0; i < 4; i++) c[mt][nt][i] = 0.f;

    const int nit = K / GH_BK;

    // prologue: stages 0,1
#pragma unroll
    for (int s = 0; s < 2; s++) {
        const int k0 = s * GH_BK;
#pragma unroll
        for (int q = 0; q < 4; q++) {
            cp16(da0 + (uint32_t)s * GH_STAGE * 2 + q * 16, aptr + k0 + q * 8, asz);
            cp16(db0 + (uint32_t)s * GH_STAGE * 2 + q * 16, bptr + k0 + q * 8, 16);
        }
        cp_commit();
    }

    int cur = 0;
    for (int it = 0; it < nit; it++) {
        if (it + 2 < nit) { asm volatile("cp.async.wait_group 1;"); }
        else              { asm volatile("cp.async.wait_group 0;"); }
        __syncthreads();

        if (it + 2 < nit) {
            int s = cur + 2; if (s >= 3) s -= 3;
            const int k0 = (it + 2) * GH_BK;
#pragma unroll
            for (int q = 0; q < 4; q++) {
                cp16(da0 + (uint32_t)s * GH_STAGE * 2 + q * 16, aptr + k0 + q * 8, asz);
                cp16(db0 + (uint32_t)s * GH_STAGE * 2 + q * 16, bptr + k0 + q * 8, 16);
            }
            cp_commit();
        }

        const uint32_t sA = sb + (uint32_t)cur * GH_STAGE * 2;
        const uint32_t sB = sA + GH_STH * 2;

#pragma unroll
        for (int kk = 0; kk < GH_BK; kk += 16) {
            uint32_t af[4][4], bf[2][4];
#pragma unroll
            for (int mt = 0; mt < 4; mt++) {
                const int rb = wm * 64 + mt * 16;
                LDSM_X4(af[mt][0], af[mt][1], af[mt][2], af[mt][3],
                        sA + a_ld_off + (uint32_t)(rb * GH_LD + kk) * 2);
            }
#pragma unroll
            for (int np = 0; np < 2; np++) {
                const int cb = wn * 32 + np * 16;
                LDSM_X4(bf[np][0], bf[np][1], bf[np][2], bf[np][3],
                        sB + b_ld_off + (uint32_t)(cb * GH_LD + kk) * 2);
            }
#pragma unroll
            for (int mt = 0; mt < 4; mt++)
#pragma unroll
                for (int np = 0; np < 2; np++) {
                    MMA_F16(c[mt][np * 2 + 0],
                            af[mt][0], af[mt][1], af[mt][2], af[mt][3],
                            bf[np][0], bf[np][1]);
                    MMA_F16(c[mt][np * 2 + 1],
                            af[mt][0], af[mt][1], af[mt][2], af[mt][3],
                            bf[np][2], bf[np][3]);
                }
        }
        cur++; if (cur == 3) cur = 0;
    }

    // epilogue (fp32)
#pragma unroll
    for (int mt = 0; mt < 4; mt++) {
        const int r0 = m0 + wm * 64 + mt * 16 + tq;
        const int r1 = r0 + 8;
#pragma unroll
        for (int nt = 0; nt < 4; nt++) {
            const int gn = n0 + wn * 32 + nt * 8 + 2 * tr;
            float2 bb = make_float2(0.f, 0.f);
            if (EPI == 1) bb = *(const float2*)(bias + gn);
            if (r0 < M) {
                float2 v = make_float2(c[mt][nt][0], c[mt][nt][1]);
                if (EPI == 1) {
                    float2 rr = *(const float2*)(resid + (size_t)r0 * Nn + gn);
                    v.x += bb.x + rr.x; v.y += bb.y + rr.y;
                }
                *(float2*)(C + (size_t)r0 * Nn + gn) = v;
            }
            if (r1 < M) {
                float2 v = make_float2(c[mt][nt][2], c[mt][nt][3]);
                if (EPI == 1) {
                    float2 rr = *(const float2*)(resid + (size_t)r1 * Nn + gn);
                    v.x += bb.x + rr.x; v.y += bb.y + rr.y;
                }
                *(float2*)(C + (size_t)r1 * Nn + gn) = v;
            }
        }
    }
}

// ---------------------------------------------------------------------------
// Tensor-core attention (R10-proven, tf32). 512 threads, block = (b,h),
// K/V loaded once, 4 q-tiles looped. Output stored as fp16 for proj GEMM.
// ---------------------------------------------------------------------------
#define QT    64
#define NKPAD 224
#define QK_LD 68
#define PV_LD 233

#define QS_OFF   0
#define KS_OFF   (QS_OFF + QT * QK_LD)
#define VT_OFF   (KS_OFF + NKPAD * QK_LD)
#define PU_OFF   (VT_OFF + HDIM * PV_LD)
#define PMAX_OFF (PU_OFF + QT * PV_LD)
#define PSUM_OFF (PMAX_OFF + 4 * QT)
#define ATTN2_SMEM_WORDS (PSUM_OFF + 4 * QT)    // 49920 w = 199680 B

__global__ __launch_bounds__(512, 1)
void attn_mma_kernel(const float* __restrict__ qkv,
                     const float* __restrict__ scale,
                     __half* __restrict__ attn_out)
{
    extern __shared__ uint32_t smw[];
    uint32_t* Qs = smw + QS_OFF;
    uint32_t* Ks = smw + KS_OFF;
    uint32_t* VT = smw + VT_OFF;
    uint32_t* Pu = smw + PU_OFF;
    float* pmax  = (float*)(smw + PMAX_OFF);
    float* psum  = (float*)(smw + PSUM_OFF);

    const int bh = blockIdx.x;
    const int b = bh / NHEAD, h = bh % NHEAD;
    const int tid = threadIdx.x;
    const int warp = tid >> 5, lane = tid & 31;
    const int tq = lane >> 2, tr = lane & 3;
    const int mf = warp & 3;
    const int ng = warp >> 2;
    const float sc = scale[h];

    // ---- load K, VT once per (b,h) ----
    for (int idx = tid; idx < NTOK * 16; idx += 512) {
        int j = idx >> 4, c4 = (idx & 15) * 4;
        float4 v = *(const float4*)(qkv + (size_t)(b * NTOK + j) * KQKV + DIM + h * HDIM + c4);
        uint32_t* p = &Ks[j * QK_LD + c4];
        p[0] = f2tf32(v.x); p[1] = f2tf32(v.y);
        p[2] = f2tf32(v.z); p[3] = f2tf32(v.w);
    }
    for (int idx = tid; idx < HDIM * 28; idx += 512) {
        int d = idx / 28, j = 196 + idx % 28;
        VT[d * PV_LD + j] = 0;
    }
    __syncthreads();
    for (int idx = tid; idx < NTOK * 16; idx += 512) {
        int j = idx >> 4, c4 = (idx & 15) * 4;
        float4 v = *(const float4*)(qkv + (size_t)(b * NTOK + j) * KQKV + 2 * DIM + h * HDIM + c4);
        VT[(c4 + 0) * PV_LD + j] = f2tf32(v.x);
        VT[(c4 + 1) * PV_LD + j] = f2tf32(v.y);
        VT[(c4 + 2) * PV_LD + j] = f2tf32(v.z);
        VT[(c4 + 3) * PV_LD + j] = f2tf32(v.w);
    }

    const int row0 = mf * 16 + tq;

    for (int qt = 0; qt < 4; qt++) {
        const int q0 = qt * QT;

        for (int idx = tid; idx < QT * 16; idx += 512) {
            int r = idx >> 4, c4 = (idx & 15) * 4;
            int q = q0 + r;
            if (q < NTOK) {
                float4 v = *(const float4*)(qkv + (size_t)(b * NTOK + q) * KQKV + h * HDIM + c4);
                uint32_t* p = &Qs[r * QK_LD + c4];
                p[0] = f2tf32(v.x * sc); p[1] = f2tf32(v.y * sc);
                p[2] = f2tf32(v.z * sc); p[3] = f2tf32(v.w * sc);
            }
        }
        __syncthreads();

        float c[7][4];
#pragma unroll
        for (int nf = 0; nf < 7; nf++)
#pragma unroll
            for (int i = 0; i < 4; i++) c[nf][i] = 0.f;

#pragma unroll
        for (int ks = 0; ks < 8; ks++) {
            const int kb = ks * 8;
            uint32_t a0 = Qs[(mf * 16 + tq) * QK_LD + kb + tr];
            uint32_t a1 = Qs[(mf * 16 + 8 + tq) * QK_LD + kb + tr];
            uint32_t a2 = Qs[(mf * 16 + tq) * QK_LD + kb + 4 + tr];
            uint32_t a3 = Qs[(mf * 16 + 8 + tq) * QK_LD + kb + 4 + tr];
#pragma unroll
            for (int nf = 0; nf < 7; nf++) {
                const int kn = ng * 56 + nf * 8 + tq;
                uint32_t b0 = Ks[kn * QK_LD + kb + tr];
                uint32_t b1 = Ks[kn * QK_LD + kb + 4 + tr];
                MMA_TF32(c[nf], a0, a1, a2, a3, b0, b1);
            }
        }

        const int i0 = q0 + mf * 16 + tq;
        const int i1 = i0 + 8;
        float mx0 = -INFINITY, mx1 = -INFINITY;
#pragma unroll
        for (int nf = 0; nf < 7; nf++) {
            const int j0 = ng * 56 + nf * 8 + 2 * tr;
            const int j1 = j0 + 1;
            c[nf][0] = (j0 >= NTOK || j0 == i0) ? -INFINITY : c[nf][0];
            c[nf][1] = (j1 >= NTOK || j1 == i0) ? -INFINITY : c[nf][1];
            c[nf][2] = (j0 >= NTOK || j0 == i1) ? -INFINITY : c[nf][2];
            c[nf][3] = (j1 >= NTOK || j1 == i1) ? -INFINITY : c[nf][3];
            mx0 = fmaxf(mx0, fmaxf(c[nf][0], c[nf][1]));
            mx1 = fmaxf(mx1, fmaxf(c[nf][2], c[nf][3]));
        }
        mx0 = fmaxf(mx0, __shfl_xor_sync(0xFFFFFFFFu, mx0, 1));
        mx0 = fmaxf(mx0, __shfl_xor_sync(0xFFFFFFFFu, mx0, 2));
        mx1 = fmaxf(mx1, __shfl_xor_sync(0xFFFFFFFFu, mx1, 1));
        mx1 = fmaxf(mx1, __shfl_xor_sync(0xFFFFFFFFu, mx1, 2));
        if (tr == 0) {
            pmax[ng * QT + row0]     = mx0;
            pmax[ng * QT + row0 + 8] = mx1;
        }
        __syncthreads();
        const float M0 = fmaxf(fmaxf(pmax[row0],          pmax[QT + row0]),
                               fmaxf(pmax[2 * QT + row0], pmax[3 * QT + row0]));
        const float M1 = fmaxf(fmaxf(pmax[row0 + 8],          pmax[QT + row0 + 8]),
                               fmaxf(pmax[2 * QT + row0 + 8], pmax[3 * QT + row0 + 8]));

        float s0 = 0.f, s1 = 0.f;
#pragma unroll
        for (int nf = 0; nf < 7; nf++) {
            c[nf][0] = __expf(c[nf][0] - M0);
            c[nf][1] = __expf(c[nf][1] - M0);
            c[nf][2] = __expf(c[nf][2] - M1);
            c[nf][3] = __expf(c[nf][3] - M1);
            s0 += c[nf][0] + c[nf][1];
            s1 += c[nf][2] + c[nf][3];
        }
        s0 += __shfl_xor_sync(0xFFFFFFFFu, s0, 1);
        s0 += __shfl_xor_sync(0xFFFFFFFFu, s0, 2);
        s1 += __shfl_xor_sync(0xFFFFFFFFu, s1, 1);
        s1 += __shfl_xor_sync(0xFFFFFFFFu, s1, 2);
        if (tr == 0) {
            psum[ng * QT + row0]     = s0;
            psum[ng * QT + row0 + 8] = s1;
        }
        __syncthreads();
        const float inv0 = 1.f / (psum[row0] + psum[QT + row0] +
                                  psum[2 * QT + row0] + psum[3 * QT + row0]);
        const float inv1 = 1.f / (psum[row0 + 8] + psum[QT + row0 + 8] +
                                  psum[2 * QT + row0 + 8] + psum[3 * QT + row0 + 8]);

#pragma unroll
        for (int nf = 0; nf < 7; nf++) {
            const int col = ng * 56 + nf * 8 + 2 * tr;
            Pu[(mf * 16 + tq) * PV_LD + col]         = f2tf32(c[nf][0] * inv0);
            Pu[(mf * 16 + tq) * PV_LD + col + 1]     = f2tf32(c[nf][1] * inv0);
            Pu[(mf * 16 + 8 + tq) * PV_LD + col]     = f2tf32(c[nf][2] * inv1);
            Pu[(mf * 16 + 8 + tq) * PV_LD + col + 1] = f2tf32(c[nf][3] * inv1);
        }
        __syncthreads();

        float o[2][4];
#pragma unroll
        for (int nf = 0; nf < 2; nf++)
#pragma unroll
            for (int i = 0; i < 4; i++) o[nf][i] = 0.f;

#pragma unroll
        for (int kc = 0; kc < 28; kc++) {
            const int kb = kc * 8;
            uint32_t a0 = Pu[(mf * 16 + tq) * PV_LD + kb + tr];
            uint32_t a1 = Pu[(mf * 16 + 8 + tq) * PV_LD + kb + tr];
            uint32_t a2 = Pu[(mf * 16 + tq) * PV_LD + kb + 4 + tr];
            uint32_t a3 = Pu[(mf * 16 + 8 + tq) * PV_LD + kb + 4 + tr];
#pragma unroll
            for (int nf = 0; nf < 2; nf++) {
                const int dn = ng * 16 + nf * 8 + tq;
                uint32_t b0 = VT[dn * PV_LD + kb + tr];
                uint32_t b1 = VT[dn * PV_LD + kb + 4 + tr];
                MMA_TF32(o[nf], a0, a1, a2, a3, b0, b1);
            }
        }

        // store O as fp16 (feeds proj GEMM A operand)
#pragma unroll
        for (int nf = 0; nf < 2; nf++) {
            const int d0 = ng * 16 + nf * 8 + 2 * tr;
            if (i0 < NTOK) {
                __half2 v = __floats2half2_rn(o[nf][0], o[nf][1]);
                *(__half2*)(attn_out + (size_t)(b * NTOK + i0) * DIM + h * HDIM + d0) = v;
            }
            if (i1 < NTOK) {
                __half2 v = __floats2half2_rn(o[nf][2], o[nf][3]);
                *(__half2*)(attn_out + (size_t)(b * NTOK + i1) * DIM + h * HDIM + d0) = v;
            }
        }
        __syncthreads();
    }
}

// ---------------------------------------------------------------------------
// Launch
// ---------------------------------------------------------------------------
extern "C" void kernel_launch(void* const* d_in, const int* in_sizes, int n_in,
                              void* d_out, int out_size)
{
    const float* x      = (const float*)d_in[0];
    const float* scale  = (const float*)d_in[1];
    const float* w_qkv  = (const float*)d_in[2];
    const float* w_proj = (const float*)d_in[3];
    const float* b_proj = (const float*)d_in[4];
    float* out = (float*)d_out;

    float* qkv_ptr = nullptr;
    __half *xh, *wqkvh, *wprojh, *attnh;
    cudaGetSymbolAddress((void**)&qkv_ptr, g_qkv);
    cudaGetSymbolAddress((void**)&xh,      g_xh);
    cudaGetSymbolAddress((void**)&wqkvh,   g_wqkvh);
    cudaGetSymbolAddress((void**)&wprojh,  g_wprojh);
    cudaGetSymbolAddress((void**)&attnh,   g_attnh);

    cudaFuncSetAttribute(gemm_f16_kernel<0>,
                         cudaFuncAttributeMaxDynamicSharedMemorySize, GH_SMEM_BYTES);
    cudaFuncSetAttribute(gemm_f16_kernel<1>,
                         cudaFuncAttributeMaxDynamicSharedMemorySize, GH_SMEM_BYTES);

    // 0) fp32 -> fp16 conversions
    {
        int n1 = MROWS * DIM;
        cvt_f2h_kernel<<<(n1 / 8 + 255) / 256, 256>>>(x, xh, n1);
        int n2 = KQKV * DIM;
        cvt_f2h_kernel<<<(n2 / 8 + 255) / 256, 256>>>(w_qkv, wqkvh, n2);
        int n3 = DIM * DIM;
        cvt_f2h_kernel<<<(n3 / 8 + 255) / 256, 256>>>(w_proj, wprojh, n3);
    }

    // 1) QKV projection (fp16 TC + ldmatrix + cp.async) -> fp32 qkv
    {
        dim3 grid(KQKV / 128, (MROWS + 127) / 128);
        gemm_f16_kernel<0><<<grid, 256, GH_SMEM_BYTES>>>(
            xh, wqkvh, qkv_ptr, MROWS, KQKV, DIM, nullptr, nullptr);
    }

    // 2) Tensor-core masked attention -> fp16 attn
    {
        size_t smem = (size_t)ATTN2_SMEM_WORDS * sizeof(uint32_t);
        cudaFuncSetAttribute(attn_mma_kernel,
                             cudaFuncAttributeMaxDynamicSharedMemorySize,
                             (int)smem);
        attn_mma_kernel<<<BATCH * NHEAD, 512, smem>>>(qkv_ptr, scale, attnh);
    }

    // 3) Output projection + bias + residual (fp16 TC) -> fp32 out
    {
        dim3 grid(DIM / 128, (MROWS + 127) / 128);
        gemm_f16_kernel<1><<<grid, 256, GH_SMEM_BYTES>>>(
            attnh, wprojh, out, MROWS, DIM, DIM, b_proj, x);
    }
}

// round 12
// speedup vs baseline: 5.1856x; 1.3411x over previous
#include <cuda_runtime.h>
#include <cuda_fp16.h>
#include <math.h>
#include <stdint.h>

// Problem constants
#define BATCH   64
#define NTOK    197
#define DIM     768
#define NHEAD   12
#define HDIM    64
#define MROWS   (BATCH * NTOK)     // 12608
#define KQKV    (3 * DIM)          // 2304

// Scratch (device globals — no allocation allowed)
__device__ __half g_qkvh[(size_t)MROWS * KQKV];   // fp16 qkv
__device__ __half g_xh[(size_t)MROWS * DIM];      // fp16 x
__device__ __half g_wqkvh[(size_t)KQKV * DIM];    // fp16 w_qkv
__device__ __half g_wprojh[(size_t)DIM * DIM];    // fp16 w_proj
__device__ __half g_attnh[(size_t)MROWS * DIM];   // fp16 attention output

// ---------------------------------------------------------------------------
// helpers
// ---------------------------------------------------------------------------
#define MMA_F16(c, a0, a1, a2, a3, b0, b1)                                   \
    asm volatile(                                                            \
        "mma.sync.aligned.m16n8k16.row.col.f32.f16.f16.f32 "                 \
        "{%0,%1,%2,%3},{%4,%5,%6,%7},{%8,%9},{%0,%1,%2,%3};"                 \
        : "+f"(c[0]), "+f"(c[1]), "+f"(c[2]), "+f"(c[3])                     \
        : "r"(a0), "r"(a1), "r"(a2), "r"(a3), "r"(b0), "r"(b1))

#define LDSM_X4(r0, r1, r2, r3, addr)                                        \
    asm volatile("ldmatrix.sync.aligned.m8n8.x4.shared.b16 "                 \
                 "{%0,%1,%2,%3}, [%4];"                                      \
                 : "=r"(r0), "=r"(r1), "=r"(r2), "=r"(r3) : "r"(addr))

// Verified (R11) ldmatrix lane->address mappings, stride parameterized (halves)
#define A_LDOFF(LD) ((uint32_t)(((lane & 15)) * (LD) + ((lane >> 4) << 3)) * 2)
#define B_LDOFF(LD) ((uint32_t)((((lane & 7) + ((lane >> 4) << 3)) * (LD)) +  \
                                (((lane >> 3) & 1) << 3)) * 2)

__device__ __forceinline__ void cp16(uint32_t dst, const void* src, int sz) {
    asm volatile("cp.async.cg.shared.global [%0], [%1], 16, %2;"
                 :: "r"(dst), "l"(src), "r"(sz));
}
__device__ __forceinline__ void cp_commit() {
    asm volatile("cp.async.commit_group;");
}

// ---------------------------------------------------------------------------
// fp32 -> fp16 converter (8 elems/thread)
// ---------------------------------------------------------------------------
__global__ void cvt_f2h_kernel(const float* __restrict__ in,
                               __half* __restrict__ out, int n)
{
    int i = (blockIdx.x * blockDim.x + threadIdx.x) * 8;
    if (i >= n) return;
    float4 v0 = *(const float4*)(in + i);
    float4 v1 = *(const float4*)(in + i + 4);
    __half2 h[4];
    h[0] = __floats2half2_rn(v0.x, v0.y);
    h[1] = __floats2half2_rn(v0.z, v0.w);
    h[2] = __floats2half2_rn(v1.x, v1.y);
    h[3] = __floats2half2_rn(v1.z, v1.w);
    *(uint4*)(out + i) = *(uint4*)h;
}

// ---------------------------------------------------------------------------
// FP16 TC GEMM (NT): C[m,n] = sum_k A[m,k]*B[n,k], fp32 accum.
// EPI==0: store fp16 (C is __half*). EPI==1: fp32 + bias[n] + resid[m,n].
// ---------------------------------------------------------------------------
#define GH_BK   64
#define GH_LD   72
#define GH_STH  (128 * GH_LD)
#define GH_STAGE (2 * GH_STH)
#define GH_SMEM_BYTES (3 * GH_STAGE * 2)

template <int EPI>
__global__ __launch_bounds__(256, 2)
void gemm_f16_kernel(const __half* __restrict__ A,
                     const __half* __restrict__ Bw,
                     void* __restrict__ Cv,
                     int M, int Nn, int K,
                     const float* __restrict__ bias,
                     const float* __restrict__ resid)
{
    extern __shared__ __half smh[];

    const int tid  = threadIdx.x;
    const int warp = tid >> 5, lane = tid & 31;
    const int wm = warp & 1;
    const int wn = warp >> 1;
    const int tq = lane >> 2;
    const int tr = lane & 3;
    const int m0 = blockIdx.y * 128;
    const int n0 = blockIdx.x * 128;

    const int lrow = tid >> 1;
    const int lcol = (tid & 1) * 32;

    const uint32_t sb = (uint32_t)__cvta_generic_to_shared(smh);
    const __half* aptr = A + (size_t)(m0 + lrow) * K + lcol;
    const __half* bptr = Bw + (size_t)(n0 + lrow) * K + lcol;
    const int asz = (m0 + lrow < M) ? 16 : 0;
    const uint32_t da0 = sb + (uint32_t)(lrow * GH_LD + lcol) * 2;
    const uint32_t db0 = da0 + GH_STH * 2;

    const uint32_t a_ld_off = A_LDOFF(GH_LD);
    const uint32_t b_ld_off = B_LDOFF(GH_LD);

    float c[4][4][4];
#pragma unroll
    for (int mt = 0; mt < 4; mt++)
#pragma unroll
        for (int nt = 0; nt < 4; nt++)
#pragma unroll
            for (int i = 0; i < 4; i++) c[mt][nt][i] = 0.f;

    const int nit = K / GH_BK;

#pragma unroll
    for (int s = 0; s < 2; s++) {
        const int k0 = s * GH_BK;
#pragma unroll
        for (int q = 0; q < 4; q++) {
            cp16(da0 + (uint32_t)s * GH_STAGE * 2 + q * 16, aptr + k0 + q * 8, asz);
            cp16(db0 + (uint32_t)s * GH_STAGE * 2 + q * 16, bptr + k0 + q * 8, 16);
        }
        cp_commit();
    }

    int cur = 0;
    for (int it = 0; it < nit; it++) {
        if (it + 2 < nit) { asm volatile("cp.async.wait_group 1;"); }
        else              { asm volatile("cp.async.wait_group 0;"); }
        __syncthreads();

        if (it + 2 < nit) {
            int s = cur + 2; if (s >= 3) s -= 3;
            const int k0 = (it + 2) * GH_BK;
#pragma unroll
            for (int q = 0; q < 4; q++) {
                cp16(da0 + (uint32_t)s * GH_STAGE * 2 + q * 16, aptr + k0 + q * 8, asz);
                cp16(db0 + (uint32_t)s * GH_STAGE * 2 + q * 16, bptr + k0 + q * 8, 16);
            }
            cp_commit();
        }

        const uint32_t sA = sb + (uint32_t)cur * GH_STAGE * 2;
        const uint32_t sB = sA + GH_STH * 2;

#pragma unroll
        for (int kk = 0; kk < GH_BK; kk += 16) {
            uint32_t af[4][4], bf[2][4];
#pragma unroll
            for (int mt = 0; mt < 4; mt++) {
                const int rb = wm * 64 + mt * 16;
                LDSM_X4(af[mt][0], af[mt][1], af[mt][2], af[mt][3],
                        sA + a_ld_off + (uint32_t)(rb * GH_LD + kk) * 2);
            }
#pragma unroll
            for (int np = 0; np < 2; np++) {
                const int cb = wn * 32 + np * 16;
                LDSM_X4(bf[np][0], bf[np][1], bf[np][2], bf[np][3],
                        sB + b_ld_off + (uint32_t)(cb * GH_LD + kk) * 2);
            }
#pragma unroll
            for (int mt = 0; mt < 4; mt++)
#pragma unroll
                for (int np = 0; np < 2; np++) {
                    MMA_F16(c[mt][np * 2 + 0],
                            af[mt][0], af[mt][1], af[mt][2], af[mt][3],
                            bf[np][0], bf[np][1]);
                    MMA_F16(c[mt][np * 2 + 1],
                            af[mt][0], af[mt][1], af[mt][2], af[mt][3],
                            bf[np][2], bf[np][3]);
                }
        }
        cur++; if (cur == 3) cur = 0;
    }

    // epilogue
#pragma unroll
    for (int mt = 0; mt < 4; mt++) {
        const int r0 = m0 + wm * 64 + mt * 16 + tq;
        const int r1 = r0 + 8;
#pragma unroll
        for (int nt = 0; nt < 4; nt++) {
            const int gn = n0 + wn * 32 + nt * 8 + 2 * tr;
            if (EPI == 0) {
                __half* Ch = (__half*)Cv;
                if (r0 < M)
                    *(__half2*)(Ch + (size_t)r0 * Nn + gn) =
                        __floats2half2_rn(c[mt][nt][0], c[mt][nt][1]);
                if (r1 < M)
                    *(__half2*)(Ch + (size_t)r1 * Nn + gn) =
                        __floats2half2_rn(c[mt][nt][2], c[mt][nt][3]);
            } else {
                float* C = (float*)Cv;
                float2 bb = *(const float2*)(bias + gn);
                if (r0 < M) {
                    float2 rr = *(const float2*)(resid + (size_t)r0 * Nn + gn);
                    float2 v = make_float2(c[mt][nt][0] + bb.x + rr.x,
                                           c[mt][nt][1] + bb.y + rr.y);
                    *(float2*)(C + (size_t)r0 * Nn + gn) = v;
                }
                if (r1 < M) {
                    float2 rr = *(const float2*)(resid + (size_t)r1 * Nn + gn);
                    float2 v = make_float2(c[mt][nt][2] + bb.x + rr.x,
                                           c[mt][nt][3] + bb.y + rr.y);
                    *(float2*)(C + (size_t)r1 * Nn + gn) = v;
                }
            }
        }
    }
}

// ---------------------------------------------------------------------------
// FP16 tensor-core attention. 512 thr, block = (b,h), K/V loaded once,
// 4 q-tiles looped. Keys padded to 256. ldmatrix + m16n8k16 for S and O.
// Scale applied to fp32 scores post-MMA. P stored fp16.
// warp = (mf q-frag 0..3, ng quarter 0..3): S keys ng*64..+64, O dims ng*16..+16.
// ---------------------------------------------------------------------------
#define NKP    256
#define AQK_LD 72     // halves: 64 + 8 pad
#define APV_LD 264    // halves: 256 + 8 pad

// half offsets
#define AQS_OFF  0                            // 64*72   = 4608
#define AKS_OFF  (AQS_OFF + 64 * AQK_LD)      // 4608
#define AVT_OFF  (AKS_OFF + NKP * AQK_LD)     // 23040
#define APU_OFF  (AVT_OFF + HDIM * APV_LD)    // 39936
#define ARED_OFF (APU_OFF + 64 * APV_LD)      // 56832 (then 512 floats)
#define ATTN_SMEM_BYTES (ARED_OFF * 2 + 512 * 4)   // 115712

__global__ __launch_bounds__(512, 1)
void attn_f16_kernel(const __half* __restrict__ qkvh,
                     const float* __restrict__ scale,
                     __half* __restrict__ attn_out)
{
    extern __shared__ __half smh_a[];
    __half* Qs = smh_a + AQS_OFF;
    __half* Ks = smh_a + AKS_OFF;
    __half* VT = smh_a + AVT_OFF;
    __half* Pu = smh_a + APU_OFF;
    float* pmax = (float*)(smh_a + ARED_OFF);       // [4][64]
    float* psum = pmax + 256;                       // [4][64]

    const int bh = blockIdx.x;
    const int b = bh / NHEAD, h = bh % NHEAD;
    const int tid = threadIdx.x;
    const int warp = tid >> 5, lane = tid & 31;
    const int tq = lane >> 2, tr = lane & 3;
    const int mf = warp & 3;
    const int ng = warp >> 2;
    const float sc = scale[h];

    const uint32_t sb  = (uint32_t)__cvta_generic_to_shared(smh_a);
    const uint32_t sQ  = sb + AQS_OFF * 2;
    const uint32_t sK  = sb + AKS_OFF * 2;
    const uint32_t sVT = sb + AVT_OFF * 2;
    const uint32_t sP  = sb + APU_OFF * 2;

    const uint4 z4 = make_uint4(0, 0, 0, 0);

    // ---- K rows (fp16 direct copy), pad rows zeroed ----
    for (int idx = tid; idx < NTOK * 8; idx += 512) {
        int j = idx >> 3, c8 = (idx & 7) * 8;
        uint4 v = *(const uint4*)(qkvh + (size_t)(b * NTOK + j) * KQKV + DIM + h * HDIM + c8);
        *(uint4*)(Ks + j * AQK_LD + c8) = v;
    }
    for (int idx = tid; idx < (NKP - NTOK) * 8; idx += 512) {
        int j = NTOK + (idx >> 3), c8 = (idx & 7) * 8;
        *(uint4*)(Ks + j * AQK_LD + c8) = z4;
    }
    // ---- VT pad cols zeroed (keys 197..255) ----
    for (int idx = tid; idx < HDIM * (NKP - NTOK); idx += 512) {
        int d = idx / (NKP - NTOK), j = NTOK + idx % (NKP - NTOK);
        VT[d * APV_LD + j] = __ushort_as_half(0);
    }
    // ---- V -> VT transpose (lane-staggered i to avoid 8-way STS conflicts) ----
    for (int idx = tid; idx < NTOK * 8; idx += 512) {
        int j = idx >> 3, c8 = (idx & 7) * 8;
        uint4 v = *(const uint4*)(qkvh + (size_t)(b * NTOK + j) * KQKV + 2 * DIM + h * HDIM + c8);
        const __half* hp = (const __half*)&v;
#pragma unroll
        for (int s = 0; s < 8; s++) {
            int i = (s + lane) & 7;
            VT[(c8 + i) * APV_LD + j] = hp[i];
        }
    }
    __syncthreads();

    const int row0 = mf * 16 + tq;
    const uint32_t a_qk = A_LDOFF(AQK_LD);
    const uint32_t b_qk = B_LDOFF(AQK_LD);
    const uint32_t a_pv = A_LDOFF(APV_LD);
    const uint32_t b_pv = B_LDOFF(APV_LD);

    for (int qt = 0; qt < 4; qt++) {
        const int q0 = qt * 64;

        // ---- Q tile (fp16 direct copy, zero-padded rows) ----
        for (int idx = tid; idx < 64 * 8; idx += 512) {
            int r = idx >> 3, c8 = (idx & 7) * 8;
            int q = q0 + r;
            uint4 v = z4;
            if (q < NTOK)
                v = *(const uint4*)(qkvh + (size_t)(b * NTOK + q) * KQKV + h * HDIM + c8);
            *(uint4*)(Qs + r * AQK_LD + c8) = v;
        }
        __syncthreads();

        // ---- S = Q K^T : 4 k-steps, 8 n-frags (64 keys) ----
        float c[8][4];
#pragma unroll
        for (int nf = 0; nf < 8; nf++)
#pragma unroll
            for (int i = 0; i < 4; i++) c[nf][i] = 0.f;

#pragma unroll
        for (int kk = 0; kk < HDIM; kk += 16) {
            uint32_t a0, a1, a2, a3;
            LDSM_X4(a0, a1, a2, a3,
                    sQ + a_qk + (uint32_t)(mf * 16 * AQK_LD + kk) * 2);
#pragma unroll
            for (int np = 0; np < 4; np++) {
                uint32_t b0, b1, b2, b3;
                LDSM_X4(b0, b1, b2, b3,
                        sK + b_qk + (uint32_t)((ng * 64 + np * 16) * AQK_LD + kk) * 2);
                MMA_F16(c[np * 2 + 0], a0, a1, a2, a3, b0, b1);
                MMA_F16(c[np * 2 + 1], a0, a1, a2, a3, b2, b3);
            }
        }

        // ---- scale + mask + quarter-max ----
        const int i0 = q0 + mf * 16 + tq;
        const int i1 = i0 + 8;
        float mx0 = -INFINITY, mx1 = -INFINITY;
#pragma unroll
        for (int nf = 0; nf < 8; nf++) {
            const int j0 = ng * 64 + nf * 8 + 2 * tr;
            const int j1 = j0 + 1;
            c[nf][0] = (j0 >= NTOK || j0 == i0) ? -INFINITY : c[nf][0] * sc;
            c[nf][1] = (j1 >= NTOK || j1 == i0) ? -INFINITY : c[nf][1] * sc;
            c[nf][2] = (j0 >= NTOK || j0 == i1) ? -INFINITY : c[nf][2] * sc;
            c[nf][3] = (j1 >= NTOK || j1 == i1) ? -INFINITY : c[nf][3] * sc;
            mx0 = fmaxf(mx0, fmaxf(c[nf][0], c[nf][1]));
            mx1 = fmaxf(mx1, fmaxf(c[nf][2], c[nf][3]));
        }
        mx0 = fmaxf(mx0, __shfl_xor_sync(0xFFFFFFFFu, mx0, 1));
        mx0 = fmaxf(mx0, __shfl_xor_sync(0xFFFFFFFFu, mx0, 2));
        mx1 = fmaxf(mx1, __shfl_xor_sync(0xFFFFFFFFu, mx1, 1));
        mx1 = fmaxf(mx1, __shfl_xor_sync(0xFFFFFFFFu, mx1, 2));
        if (tr == 0) {
            pmax[ng * 64 + row0]     = mx0;
            pmax[ng * 64 + row0 + 8] = mx1;
        }
        __syncthreads();
        const float M0 = fmaxf(fmaxf(pmax[row0],           pmax[64 + row0]),
                               fmaxf(pmax[128 + row0],     pmax[192 + row0]));
        const float M1 = fmaxf(fmaxf(pmax[row0 + 8],       pmax[64 + row0 + 8]),
                               fmaxf(pmax[128 + row0 + 8], pmax[192 + row0 + 8]));

        // ---- exp + quarter-sum ----
        float s0 = 0.f, s1 = 0.f;
#pragma unroll
        for (int nf = 0; nf < 8; nf++) {
            c[nf][0] = __expf(c[nf][0] - M0);
            c[nf][1] = __expf(c[nf][1] - M0);
            c[nf][2] = __expf(c[nf][2] - M1);
            c[nf][3] = __expf(c[nf][3] - M1);
            s0 += c[nf][0] + c[nf][1];
            s1 += c[nf][2] + c[nf][3];
        }
        s0 += __shfl_xor_sync(0xFFFFFFFFu, s0, 1);
        s0 += __shfl_xor_sync(0xFFFFFFFFu, s0, 2);
        s1 += __shfl_xor_sync(0xFFFFFFFFu, s1, 1);
        s1 += __shfl_xor_sync(0xFFFFFFFFu, s1, 2);
        if (tr == 0) {
            psum[ng * 64 + row0]     = s0;
            psum[ng * 64 + row0 + 8] = s1;
        }
        __syncthreads();
        const float inv0 = 1.f / (psum[row0] + psum[64 + row0] +
                                  psum[128 + row0] + psum[192 + row0]);
        const float inv1 = 1.f / (psum[row0 + 8] + psum[64 + row0 + 8] +
                                  psum[128 + row0 + 8] + psum[192 + row0 + 8]);

        // ---- P (fp16, normalized) ----
#pragma unroll
        for (int nf = 0; nf < 8; nf++) {
            const int col = ng * 64 + nf * 8 + 2 * tr;
            *(__half2*)(Pu + (mf * 16 + tq) * APV_LD + col) =
                __floats2half2_rn(c[nf][0] * inv0, c[nf][1] * inv0);
            *(__half2*)(Pu + (mf * 16 + 8 + tq) * APV_LD + col) =
                __floats2half2_rn(c[nf][2] * inv1, c[nf][3] * inv1);
        }
        __syncthreads();

        // ---- O = P V^T : 16 k-steps, dims ng*16..+16 ----
        float o[2][4];
#pragma unroll
        for (int nf = 0; nf < 2; nf++)
#pragma unroll
            for (int i = 0; i < 4; i++) o[nf][i] = 0.f;

#pragma unroll
        for (int kk = 0; kk < NKP; kk += 16) {
            uint32_t a0, a1, a2, a3, b0, b1, b2, b3;
            LDSM_X4(a0, a1, a2, a3,
                    sP + a_pv + (uint32_t)(mf * 16 * APV_LD + kk) * 2);
            LDSM_X4(b0, b1, b2, b3,
                    sVT + b_pv + (uint32_t)(ng * 16 * APV_LD + kk) * 2);
            MMA_F16(o[0], a0, a1, a2, a3, b0, b1);
            MMA_F16(o[1], a0, a1, a2, a3, b2, b3);
        }

        // ---- store O (fp16) ----
#pragma unroll
        for (int nf = 0; nf < 2; nf++) {
            const int d0 = ng * 16 + nf * 8 + 2 * tr;
            if (i0 < NTOK)
                *(__half2*)(attn_out + (size_t)(b * NTOK + i0) * DIM + h * HDIM + d0) =
                    __floats2half2_rn(o[nf][0], o[nf][1]);
            if (i1 < NTOK)
                *(__half2*)(attn_out + (size_t)(b * NTOK + i1) * DIM + h * HDIM + d0) =
                    __floats2half2_rn(o[nf][2], o[nf][3]);
        }
        __syncthreads();
    }
}

// ---------------------------------------------------------------------------
// Launch
// ---------------------------------------------------------------------------
extern "C" void kernel_launch(void* const* d_in, const int* in_sizes, int n_in,
                              void* d_out, int out_size)
{
    const float* x      = (const float*)d_in[0];
    const float* scale  = (const float*)d_in[1];
    const float* w_qkv  = (const float*)d_in[2];
    const float* w_proj = (const float*)d_in[3];
    const float* b_proj = (const float*)d_in[4];
    float* out = (float*)d_out;

    __half *qkvh, *xh, *wqkvh, *wprojh, *attnh;
    cudaGetSymbolAddress((void**)&qkvh,   g_qkvh);
    cudaGetSymbolAddress((void**)&xh,     g_xh);
    cudaGetSymbolAddress((void**)&wqkvh,  g_wqkvh);
    cudaGetSymbolAddress((void**)&wprojh, g_wprojh);
    cudaGetSymbolAddress((void**)&attnh,  g_attnh);

    cudaFuncSetAttribute(gemm_f16_kernel<0>,
                         cudaFuncAttributeMaxDynamicSharedMemorySize, GH_SMEM_BYTES);
    cudaFuncSetAttribute(gemm_f16_kernel<1>,
                         cudaFuncAttributeMaxDynamicSharedMemorySize, GH_SMEM_BYTES);
    cudaFuncSetAttribute(attn_f16_kernel,
                         cudaFuncAttributeMaxDynamicSharedMemorySize, ATTN_SMEM_BYTES);

    // 0) fp32 -> fp16 conversions
    {
        int n1 = MROWS * DIM;
        cvt_f2h_kernel<<<(n1 / 8 + 255) / 256, 256>>>(x, xh, n1);
        int n2 = KQKV * DIM;
        cvt_f2h_kernel<<<(n2 / 8 + 255) / 256, 256>>>(w_qkv, wqkvh, n2);
        int n3 = DIM * DIM;
        cvt_f2h_kernel<<<(n3 / 8 + 255) / 256, 256>>>(w_proj, wprojh, n3);
    }

    // 1) QKV projection -> fp16 qkv
    {
        dim3 grid(KQKV / 128, (MROWS + 127) / 128);
        gemm_f16_kernel<0><<<grid, 256, GH_SMEM_BYTES>>>(
            xh, wqkvh, qkvh, MROWS, KQKV, DIM, nullptr, nullptr);
    }

    // 2) FP16 tensor-core masked attention -> fp16 attn
    attn_f16_kernel<<<BATCH * NHEAD, 512, ATTN_SMEM_BYTES>>>(qkvh, scale, attnh);

    // 3) Output projection + bias + residual -> fp32 out
    {
        dim3 grid(DIM / 128, (MROWS + 127) / 128);
        gemm_f16_kernel<1><<<grid, 256, GH_SMEM_BYTES>>>(
            attnh, wprojh, out, MROWS, DIM, DIM, b_proj, x);
    }
}